// round 11
// baseline (speedup 1.0000x reference)
#include <cuda_runtime.h>
#include <cuda_bf16.h>
#include <cuda_fp16.h>
#include <math.h>
#include <stdint.h>

// ---------------- problem constants ----------------
#define MAXN 50000
#define NPAD 50048              // 391*128 padded rows (scratch only)
#define MAXE 800000
#define MAXTOT (MAXE + MAXN)

// ---------------- device scratch ----------------
__device__ __half g_xwh[(size_t)NPAD * 256]; // xw of current layer (fp16, gathered)
__device__ __half g_hh[(size_t)NPAD * 256];  // layer-1 output (fp16)
__device__ __nv_bfloat16 g_bth[32768];       // W^T hi  [N][K]
__device__ __nv_bfloat16 g_btl[32768];       // W^T lo  [N][K]
__device__ float g_asrc[MAXN];
__device__ float g_adst[MAXN];
__device__ int   g_cnt[MAXN];
__device__ int   g_off[MAXN + 1];
__device__ int   g_csrc[MAXTOT];
__device__ int   g_bsum[64];
__device__ int   g_total;
__device__ int   g_is64;

// ---------------- mma / ldmatrix helpers ----------------
__device__ __forceinline__ uint32_t smem_u32(const void* p) {
    uint32_t a;
    asm("{ .reg .u64 t; cvta.to.shared.u64 t, %1; cvt.u32.u64 %0, t; }" : "=r"(a) : "l"(p));
    return a;
}
__device__ __forceinline__ void ldsm4(uint32_t* r, uint32_t addr) {
    asm volatile("ldmatrix.sync.aligned.m8n8.x4.shared.b16 {%0,%1,%2,%3}, [%4];"
        : "=r"(r[0]), "=r"(r[1]), "=r"(r[2]), "=r"(r[3]) : "r"(addr));
}
__device__ __forceinline__ void mma16816(float* c, const uint32_t* a, const uint32_t* b) {
    asm volatile("mma.sync.aligned.m16n8k16.row.col.f32.bf16.bf16.f32 "
        "{%0,%1,%2,%3}, {%4,%5,%6,%7}, {%8,%9}, {%0,%1,%2,%3};"
        : "+f"(c[0]), "+f"(c[1]), "+f"(c[2]), "+f"(c[3])
        : "r"(a[0]), "r"(a[1]), "r"(a[2]), "r"(a[3]), "r"(b[0]), "r"(b[1]));
}

// generic 8-element A row loader -> fp32
__device__ __forceinline__ void load_a8(const float* ap, float* v) {
    *(float4*)v       = *(const float4*)ap;
    *(float4*)(v + 4) = *(const float4*)(ap + 4);
}
__device__ __forceinline__ void load_a8(const __half* ap, float* v) {
    uint4 u = *(const uint4*)ap;
    const __half2* h = (const __half2*)&u;
    #pragma unroll
    for (int q = 0; q < 4; q++) {
        float2 f = __half22float2(h[q]);
        v[2*q] = f.x; v[2*q+1] = f.y;
    }
}

// ---------------- dtype detection ----------------
__global__ void detect_kernel(const int* __restrict__ ei) {
    if (threadIdx.x == 0 && blockIdx.x == 0) {
        int z = 1;
        #pragma unroll
        for (int i = 1; i < 64; i += 2)
            if (ei[i] != 0) z = 0;
        g_is64 = z;
    }
}
__device__ __forceinline__ int load_idx(const int* __restrict__ ei, long long elem, int is64) {
    return is64 ? ei[2 * elem] : ei[elem];
}

// ---------------- CSR build ----------------
__global__ void init_kernel(int n) {
    int i = blockIdx.x * blockDim.x + threadIdx.x;
    if (i < n) { g_cnt[i] = 1; g_asrc[i] = 0.f; g_adst[i] = 0.f; }
}
__global__ void zero_alpha_kernel(int n) {
    int i = blockIdx.x * blockDim.x + threadIdx.x;
    if (i < n) { g_asrc[i] = 0.f; g_adst[i] = 0.f; }
}
__global__ void hist_kernel(const int* __restrict__ ei, int E) {
    int i = blockIdx.x * blockDim.x + threadIdx.x;
    if (i >= E) return;
    int d = load_idx(ei, (long long)E + i, g_is64);
    atomicAdd(&g_cnt[d], 1);
}
__global__ __launch_bounds__(1024) void blockscan_kernel(int n) {
    __shared__ int warpsum[32];
    int i = blockIdx.x * 1024 + threadIdx.x;
    int v = (i < n) ? g_cnt[i] : 0;
    int lane = threadIdx.x & 31, wid = threadIdx.x >> 5;
    int s = v;
    #pragma unroll
    for (int o = 1; o < 32; o <<= 1) {
        int t = __shfl_up_sync(~0u, s, o);
        if (lane >= o) s += t;
    }
    if (lane == 31) warpsum[wid] = s;
    __syncthreads();
    if (wid == 0) {
        int ws = warpsum[lane];
        #pragma unroll
        for (int o = 1; o < 32; o <<= 1) {
            int t = __shfl_up_sync(~0u, ws, o);
            if (lane >= o) ws += t;
        }
        warpsum[lane] = ws;
    }
    __syncthreads();
    int excl = s - v + (wid ? warpsum[wid - 1] : 0);
    if (i < n) g_off[i] = excl;
    if (threadIdx.x == 1023) g_bsum[blockIdx.x] = excl + v;
}
__global__ void scanb_kernel(int nb) {
    if (threadIdx.x == 0 && blockIdx.x == 0) {
        int run = 0;
        for (int b = 0; b < nb; b++) { int t = g_bsum[b]; g_bsum[b] = run; run += t; }
        g_total = run;
    }
}
__global__ void finish_off_kernel(int n) {
    int i = blockIdx.x * 1024 + threadIdx.x;
    if (i < n) {
        int off = g_off[i] + g_bsum[i >> 10];
        g_off[i] = off;
        g_csrc[off] = i;
        g_cnt[i] = off + 1;
    }
    if (i == 0) g_off[n] = g_total;
}
__global__ void scatter_kernel(const int* __restrict__ ei, int E) {
    int i = blockIdx.x * blockDim.x + threadIdx.x;
    if (i >= E) return;
    int is64 = g_is64;
    int s = load_idx(ei, i, is64);
    int d = load_idx(ei, (long long)E + i, is64);
    int p = atomicAdd(&g_cnt[d], 1);
    g_csrc[p] = s;
}

// ---------------- W^T split: W[K][N] fp32 -> g_bth/g_btl [N][K] bf16 ----------
__global__ void wt_split_kernel(const float* __restrict__ W, int K, int N) {
    int i = blockIdx.x * blockDim.x + threadIdx.x;
    if (i >= N * K) return;
    int nn = i / K, kk = i - nn * K;
    float v = W[(size_t)kk * N + nn];
    __nv_bfloat16 h = __float2bfloat16(v);
    g_bth[i] = h;
    g_btl[i] = __float2bfloat16(v - __bfloat162float(h));
}

// ---- GEMM: block 128x128, 8 warps (2Mx4N), warp 64x32, mma.sync, hi/lo bf16 --
#define LDAB 48
#define OFF_AL 6144
#define OFF_BH 12288
#define OFF_BL 18432
#define STAGE_B 24576
#define SMEM_DYN (2 * STAGE_B)

template<typename TA>
__global__ __launch_bounds__(256, 2) void gemm_mma_kernel(
    const TA* __restrict__ A, int Kfull,
    const __nv_bfloat16* __restrict__ Bth, const __nv_bfloat16* __restrict__ Btl,
    __half* __restrict__ C,
    const float* __restrict__ avs, const float* __restrict__ avd,
    int M, int N)
{
    extern __shared__ __align__(16) char buf[];
    uint32_t sb = smem_u32(buf);

    int tid = threadIdx.x;
    int w = tid >> 5, lane = tid & 31;
    int wr = w >> 2, wc = w & 3;                 // warp tile 64(M) x 32(N)
    int r0 = blockIdx.x * 128, c0 = blockIdx.y * 128;

    float acc[4][4][4];
    #pragma unroll
    for (int mt = 0; mt < 4; mt++)
        #pragma unroll
        for (int nt = 0; nt < 4; nt++)
            #pragma unroll
            for (int q = 0; q < 4; q++) acc[mt][nt][q] = 0.f;

    int s_row = tid >> 1, s_half = (tid & 1) * 8;

    // ldmatrix lane offsets — A pattern (m16k16)
    int la_row = (lane & 15), la_k = (lane >> 4) * 8;
    uint32_t a_frag_off = (uint32_t)(la_row * LDAB + la_k * 2);
    // B pattern (n16k16)
    int lb_n = (lane & 7) + ((lane >> 4) & 1) * 8;
    int lb_k = ((lane >> 3) & 1) * 8;
    uint32_t b_frag_off = (uint32_t)(lb_n * LDAB + lb_k * 2);

    float arv[8];
    uint4 bh_rv, bl_rv;
    int steps = Kfull / 16;

    {   // prologue: k-step 0
        int gr = r0 + s_row;
        #pragma unroll
        for (int q = 0; q < 8; q++) arv[q] = 0.f;
        if (gr < M) load_a8(A + (size_t)gr * Kfull + s_half, arv);
        size_t bo = (size_t)(c0 + s_row) * Kfull + s_half;
        bh_rv = *(const uint4*)(Bth + bo);
        bl_rv = *(const uint4*)(Btl + bo);
    }
    {   // store stage 0
        char* st = buf;
        __nv_bfloat16 hs[8], ls[8];
        #pragma unroll
        for (int q = 0; q < 8; q++) {
            hs[q] = __float2bfloat16(arv[q]);
            ls[q] = __float2bfloat16(arv[q] - __bfloat162float(hs[q]));
        }
        *(uint4*)(st + s_row * LDAB + s_half * 2)          = *(uint4*)hs;
        *(uint4*)(st + OFF_AL + s_row * LDAB + s_half * 2) = *(uint4*)ls;
        *(uint4*)(st + OFF_BH + s_row * LDAB + s_half * 2) = bh_rv;
        *(uint4*)(st + OFF_BL + s_row * LDAB + s_half * 2) = bl_rv;
    }
    __syncthreads();

    for (int i = 0; i < steps; i++) {
        int cur = i & 1, nxt = cur ^ 1;
        if (i + 1 < steps) {
            int k0 = (i + 1) * 16;
            int gr = r0 + s_row;
            #pragma unroll
            for (int q = 0; q < 8; q++) arv[q] = 0.f;
            if (gr < M) load_a8(A + (size_t)gr * Kfull + k0 + s_half, arv);
            size_t bo = (size_t)(c0 + s_row) * Kfull + k0 + s_half;
            bh_rv = *(const uint4*)(Bth + bo);
            bl_rv = *(const uint4*)(Btl + bo);
        }
        {
            uint32_t st = sb + cur * STAGE_B;
            uint32_t bh[2][4], bl[2][4];
            #pragma unroll
            for (int np = 0; np < 2; np++) {
                uint32_t nbase = st + OFF_BH + (uint32_t)((wc * 32 + np * 16) * LDAB) + b_frag_off;
                ldsm4(bh[np], nbase);
                ldsm4(bl[np], nbase + (OFF_BL - OFF_BH));
            }
            #pragma unroll
            for (int mt = 0; mt < 4; mt++) {
                uint32_t ah[4], al[4];
                uint32_t rbase = st + (uint32_t)((wr * 64 + mt * 16) * LDAB) + a_frag_off;
                ldsm4(ah, rbase);
                ldsm4(al, rbase + OFF_AL);
                #pragma unroll
                for (int nt = 0; nt < 4; nt++) {
                    const uint32_t* bhp = &bh[nt >> 1][(nt & 1) * 2];
                    const uint32_t* blp = &bl[nt >> 1][(nt & 1) * 2];
                    mma16816(acc[mt][nt], ah, bhp);
                    mma16816(acc[mt][nt], ah, blp);
                    mma16816(acc[mt][nt], al, bhp);
                }
            }
        }
        if (i + 1 < steps) {
            char* st = buf + nxt * STAGE_B;
            __nv_bfloat16 hs[8], ls[8];
            #pragma unroll
            for (int q = 0; q < 8; q++) {
                hs[q] = __float2bfloat16(arv[q]);
                ls[q] = __float2bfloat16(arv[q] - __bfloat162float(hs[q]));
            }
            *(uint4*)(st + s_row * LDAB + s_half * 2)          = *(uint4*)hs;
            *(uint4*)(st + OFF_AL + s_row * LDAB + s_half * 2) = *(uint4*)ls;
            *(uint4*)(st + OFF_BH + s_row * LDAB + s_half * 2) = bh_rv;
            *(uint4*)(st + OFF_BL + s_row * LDAB + s_half * 2) = bl_rv;
        }
        __syncthreads();
    }

    // ---- store C (fp16) + fused alpha partials from fp32 accumulators ----
    {
        float as[4][2], ad[4][2];
        #pragma unroll
        for (int nt = 0; nt < 4; nt++) {
            int col = c0 + wc * 32 + nt * 8 + (lane & 3) * 2;
            as[nt][0] = avs[col];     as[nt][1] = avs[col + 1];
            ad[nt][0] = avd[col];     ad[nt][1] = avd[col + 1];
        }
        #pragma unroll
        for (int mt = 0; mt < 4; mt++) {
            int rA = r0 + wr * 64 + mt * 16 + (lane >> 2);
            int rB = rA + 8;
            float ssA = 0.f, sdA = 0.f, ssB = 0.f, sdB = 0.f;
            #pragma unroll
            for (int nt = 0; nt < 4; nt++) {
                float* c = acc[mt][nt];
                int col = c0 + wc * 32 + nt * 8 + (lane & 3) * 2;
                *(__half2*)(C + (size_t)rA * N + col) = __floats2half2_rn(c[0], c[1]);
                *(__half2*)(C + (size_t)rB * N + col) = __floats2half2_rn(c[2], c[3]);
                ssA += c[0] * as[nt][0] + c[1] * as[nt][1];
                sdA += c[0] * ad[nt][0] + c[1] * ad[nt][1];
                ssB += c[2] * as[nt][0] + c[3] * as[nt][1];
                sdB += c[2] * ad[nt][0] + c[3] * ad[nt][1];
            }
            #pragma unroll
            for (int o = 1; o < 4; o <<= 1) {
                ssA += __shfl_xor_sync(~0u, ssA, o);
                sdA += __shfl_xor_sync(~0u, sdA, o);
                ssB += __shfl_xor_sync(~0u, ssB, o);
                sdB += __shfl_xor_sync(~0u, sdB, o);
            }
            if ((lane & 3) == 0) {
                if (rA < M) { atomicAdd(&g_asrc[rA], ssA); atomicAdd(&g_adst[rA], sdA); }
                if (rB < M) { atomicAdd(&g_asrc[rB], ssB); atomicAdd(&g_adst[rB], sdB); }
            }
        }
    }
}

// -- fused softmax + aggregation (warp per node, fp16 gather, fp32 accumulate)
template<int F, bool RELU, typename OutT>
__global__ void agg_kernel(const __half* __restrict__ xw,
                           const float* __restrict__ bias,
                           OutT* __restrict__ out, int n)
{
    int w = (blockIdx.x * blockDim.x + threadIdx.x) >> 5;
    int lane = threadIdx.x & 31;
    if (w >= n) return;
    const int NV = F / 32;                      // halves per lane (8 or 4)
    int beg = g_off[w], end = g_off[w + 1];
    float adi = g_adst[w];

    // ---- pass 1: online softmax stats over this node's edges ----
    float mx = -1e30f, sm = 0.f;
    for (int k = beg + lane; k < end; k += 32) {
        int s = g_csrc[k];
        float e = g_asrc[s] + adi;
        e = e >= 0.f ? e : 0.2f * e;
        if (e > mx) { sm = sm * __expf(mx - e) + 1.f; mx = e; }
        else        { sm += __expf(e - mx); }
    }
    #pragma unroll
    for (int o = 16; o; o >>= 1) {
        float mo = __shfl_xor_sync(~0u, mx, o);
        float so = __shfl_xor_sync(~0u, sm, o);
        float nm = fmaxf(mx, mo);
        sm = sm * __expf(mx - nm) + so * __expf(mo - nm);
        mx = nm;
    }
    float inv = 1.f / sm;

    // ---- pass 2: gather + accumulate, att recomputed inline ----
    float acc[NV];
    #pragma unroll
    for (int q = 0; q < NV; q++) acc[q] = 0.f;

    int k = beg;
    for (; k + 2 <= end; k += 2) {
        int s0 = g_csrc[k], s1 = g_csrc[k + 1];
        float e0 = g_asrc[s0] + adi;  e0 = e0 >= 0.f ? e0 : 0.2f * e0;
        float e1 = g_asrc[s1] + adi;  e1 = e1 >= 0.f ? e1 : 0.2f * e1;
        float a0 = __expf(e0 - mx) * inv;
        float a1 = __expf(e1 - mx) * inv;
        const __half* r0p = xw + (size_t)s0 * F + lane * NV;
        const __half* r1p = xw + (size_t)s1 * F + lane * NV;
        if (NV == 8) {
            uint4 u0 = *(const uint4*)r0p;
            uint4 u1 = *(const uint4*)r1p;
            const __half2* h0 = (const __half2*)&u0;
            const __half2* h1 = (const __half2*)&u1;
            #pragma unroll
            for (int q = 0; q < 4; q++) {
                float2 f0 = __half22float2(h0[q]);
                float2 f1 = __half22float2(h1[q]);
                acc[2*q]   += a0 * f0.x + a1 * f1.x;
                acc[2*q+1] += a0 * f0.y + a1 * f1.y;
            }
        } else {
            uint2 u0 = *(const uint2*)r0p;
            uint2 u1 = *(const uint2*)r1p;
            const __half2* h0 = (const __half2*)&u0;
            const __half2* h1 = (const __half2*)&u1;
            #pragma unroll
            for (int q = 0; q < 2; q++) {
                float2 f0 = __half22float2(h0[q]);
                float2 f1 = __half22float2(h1[q]);
                acc[2*q]   += a0 * f0.x + a1 * f1.x;
                acc[2*q+1] += a0 * f0.y + a1 * f1.y;
            }
        }
    }
    if (k < end) {
        int s0 = g_csrc[k];
        float e0 = g_asrc[s0] + adi;  e0 = e0 >= 0.f ? e0 : 0.2f * e0;
        float a0 = __expf(e0 - mx) * inv;
        const __half* r0p = xw + (size_t)s0 * F + lane * NV;
        if (NV == 8) {
            uint4 u0 = *(const uint4*)r0p;
            const __half2* h0 = (const __half2*)&u0;
            #pragma unroll
            for (int q = 0; q < 4; q++) {
                float2 f0 = __half22float2(h0[q]);
                acc[2*q]   += a0 * f0.x;
                acc[2*q+1] += a0 * f0.y;
            }
        } else {
            uint2 u0 = *(const uint2*)r0p;
            const __half2* h0 = (const __half2*)&u0;
            #pragma unroll
            for (int q = 0; q < 2; q++) {
                float2 f0 = __half22float2(h0[q]);
                acc[2*q]   += a0 * f0.x;
                acc[2*q+1] += a0 * f0.y;
            }
        }
    }

    // ---- bias + relu + store ----
    const float* bp = bias + lane * NV;
    #pragma unroll
    for (int q = 0; q < NV; q++) {
        float v = acc[q] + bp[q];
        if (RELU) v = fmaxf(v, 0.f);
        acc[q] = v;
    }
    if (sizeof(OutT) == 2) {
        __half* op = (__half*)out + (size_t)w * F + lane * NV;
        #pragma unroll
        for (int q = 0; q < NV; q += 2)
            *(__half2*)(op + q) = __floats2half2_rn(acc[q], acc[q+1]);
    } else {
        float* op = (float*)out + (size_t)w * F + lane * NV;
        #pragma unroll
        for (int q = 0; q < NV; q += 4)
            *(float4*)(op + q) = make_float4(acc[q], acc[q+1], acc[q+2], acc[q+3]);
    }
}

// ---------------- launch ----------------
extern "C" void kernel_launch(void* const* d_in, const int* in_sizes, int n_in,
                              void* d_out, int out_size) {
    const float* x   = (const float*)d_in[0];
    const int*   ei  = (const int*)d_in[1];
    const float* W1  = (const float*)d_in[2];
    const float* a1s = (const float*)d_in[3];
    const float* a1d = (const float*)d_in[4];
    const float* b1  = (const float*)d_in[5];
    const float* W2  = (const float*)d_in[6];
    const float* a2s = (const float*)d_in[7];
    const float* a2d = (const float*)d_in[8];
    const float* b2  = (const float*)d_in[9];
    float* out = (float*)d_out;

    int n = in_sizes[0] / 128;        // 50000
    int E = in_sizes[1] / 2;          // 800000

    __half *p_xwh = nullptr, *p_hh = nullptr;
    __nv_bfloat16 *p_bth = nullptr, *p_btl = nullptr;
    cudaGetSymbolAddress((void**)&p_xwh, g_xwh);
    cudaGetSymbolAddress((void**)&p_hh,  g_hh);
    cudaGetSymbolAddress((void**)&p_bth, g_bth);
    cudaGetSymbolAddress((void**)&p_btl, g_btl);

    cudaFuncSetAttribute(gemm_mma_kernel<float>,  cudaFuncAttributeMaxDynamicSharedMemorySize, SMEM_DYN);
    cudaFuncSetAttribute(gemm_mma_kernel<__half>, cudaFuncAttributeMaxDynamicSharedMemorySize, SMEM_DYN);

    int nblk    = (n + 255) / 256;
    int eblk    = (E + 255) / 256;
    int warpBlk = (n * 32 + 255) / 256;
    int sblk    = (n + 1023) / 1024;
    int rtiles  = (n + 127) / 128;    // 391
    dim3 g1(rtiles, 2);               // layer1: N=256
    dim3 g2(rtiles, 1);               // layer2: N=128

    // gemm1 lands in ncu's profiled slot (4th launch)
    detect_kernel<<<1, 32>>>(ei);
    init_kernel<<<nblk, 256>>>(n);
    wt_split_kernel<<<(128 * 256 + 255) / 256, 256>>>(W1, 128, 256);
    gemm_mma_kernel<float><<<g1, 256, SMEM_DYN>>>(x, 128, p_bth, p_btl, p_xwh, a1s, a1d, n, 256);
    hist_kernel<<<eblk, 256>>>(ei, E);
    blockscan_kernel<<<sblk, 1024>>>(n);
    scanb_kernel<<<1, 32>>>(sblk);
    finish_off_kernel<<<sblk, 1024>>>(n);
    scatter_kernel<<<eblk, 256>>>(ei, E);

    // ---- layer 1 tail: fused softmax+agg -> h (fp16) ----
    agg_kernel<256, true, __half><<<warpBlk, 256>>>(p_xwh, b1, p_hh, n);
    zero_alpha_kernel<<<nblk, 256>>>(n);

    // ---- layer 2 ----
    wt_split_kernel<<<(256 * 128 + 255) / 256, 256>>>(W2, 256, 128);
    gemm_mma_kernel<__half><<<g2, 256, SMEM_DYN>>>(p_hh, 256, p_bth, p_btl, p_xwh, a2s, a2d, n, 128);
    agg_kernel<128, false, float><<<warpBlk, 256>>>(p_xwh, b2, out, n);
}

// round 12
// speedup vs baseline: 1.0170x; 1.0170x over previous
#include <cuda_runtime.h>
#include <cuda_bf16.h>
#include <cuda_fp16.h>
#include <math.h>
#include <stdint.h>

// ---------------- problem constants ----------------
#define MAXN 50000
#define NPAD 50048              // 391*128 padded rows (scratch only)
#define MAXE 800000
#define MAXTOT (MAXE + MAXN)

// ---------------- device scratch ----------------
__device__ __half g_xwh[(size_t)NPAD * 256]; // xw of current layer (fp16, gathered)
__device__ __half g_hh[(size_t)NPAD * 256];  // layer-1 output (fp16)
__device__ __nv_bfloat16 g_bth[32768];       // W^T hi  [N][K]
__device__ __nv_bfloat16 g_btl[32768];       // W^T lo  [N][K]
__device__ float g_asrc[MAXN];
__device__ float g_adst[MAXN];
__device__ float g_att[MAXTOT];
__device__ int   g_cnt[MAXN];
__device__ int   g_off[MAXN + 1];
__device__ int   g_csrc[MAXTOT];
__device__ int   g_bsum[64];
__device__ int   g_total;
__device__ int   g_is64;

// ---------------- mma / ldmatrix helpers ----------------
__device__ __forceinline__ uint32_t smem_u32(const void* p) {
    uint32_t a;
    asm("{ .reg .u64 t; cvta.to.shared.u64 t, %1; cvt.u32.u64 %0, t; }" : "=r"(a) : "l"(p));
    return a;
}
__device__ __forceinline__ void ldsm4(uint32_t* r, uint32_t addr) {
    asm volatile("ldmatrix.sync.aligned.m8n8.x4.shared.b16 {%0,%1,%2,%3}, [%4];"
        : "=r"(r[0]), "=r"(r[1]), "=r"(r[2]), "=r"(r[3]) : "r"(addr));
}
__device__ __forceinline__ void mma16816(float* c, const uint32_t* a, const uint32_t* b) {
    asm volatile("mma.sync.aligned.m16n8k16.row.col.f32.bf16.bf16.f32 "
        "{%0,%1,%2,%3}, {%4,%5,%6,%7}, {%8,%9}, {%0,%1,%2,%3};"
        : "+f"(c[0]), "+f"(c[1]), "+f"(c[2]), "+f"(c[3])
        : "r"(a[0]), "r"(a[1]), "r"(a[2]), "r"(a[3]), "r"(b[0]), "r"(b[1]));
}

// 8-element A row loader -> fp32 (fp32 or fp16 source)
__device__ __forceinline__ void load_a8(const float* ap, float* v) {
    *(float4*)v       = *(const float4*)ap;
    *(float4*)(v + 4) = *(const float4*)(ap + 4);
}
__device__ __forceinline__ void load_a8(const __half* ap, float* v) {
    uint4 u = *(const uint4*)ap;
    const __half2* h = (const __half2*)&u;
    #pragma unroll
    for (int q = 0; q < 4; q++) {
        float2 f = __half22float2(h[q]);
        v[2*q] = f.x; v[2*q+1] = f.y;
    }
}

// ---------------- dtype detection ----------------
__global__ void detect_kernel(const int* __restrict__ ei) {
    if (threadIdx.x == 0 && blockIdx.x == 0) {
        int z = 1;
        #pragma unroll
        for (int i = 1; i < 64; i += 2)
            if (ei[i] != 0) z = 0;
        g_is64 = z;
    }
}
__device__ __forceinline__ int load_idx(const int* __restrict__ ei, long long elem, int is64) {
    return is64 ? ei[2 * elem] : ei[elem];
}

// ---------------- CSR build ----------------
__global__ void init_kernel(int n) {
    int i = blockIdx.x * blockDim.x + threadIdx.x;
    if (i < n) { g_cnt[i] = 1; g_asrc[i] = 0.f; g_adst[i] = 0.f; }
}
__global__ void zero_alpha_kernel(int n) {
    int i = blockIdx.x * blockDim.x + threadIdx.x;
    if (i < n) { g_asrc[i] = 0.f; g_adst[i] = 0.f; }
}
__global__ void hist_kernel(const int* __restrict__ ei, int E) {
    int i = blockIdx.x * blockDim.x + threadIdx.x;
    if (i >= E) return;
    int d = load_idx(ei, (long long)E + i, g_is64);
    atomicAdd(&g_cnt[d], 1);
}
__global__ __launch_bounds__(1024) void blockscan_kernel(int n) {
    __shared__ int warpsum[32];
    int i = blockIdx.x * 1024 + threadIdx.x;
    int v = (i < n) ? g_cnt[i] : 0;
    int lane = threadIdx.x & 31, wid = threadIdx.x >> 5;
    int s = v;
    #pragma unroll
    for (int o = 1; o < 32; o <<= 1) {
        int t = __shfl_up_sync(~0u, s, o);
        if (lane >= o) s += t;
    }
    if (lane == 31) warpsum[wid] = s;
    __syncthreads();
    if (wid == 0) {
        int ws = warpsum[lane];
        #pragma unroll
        for (int o = 1; o < 32; o <<= 1) {
            int t = __shfl_up_sync(~0u, ws, o);
            if (lane >= o) ws += t;
        }
        warpsum[lane] = ws;
    }
    __syncthreads();
    int excl = s - v + (wid ? warpsum[wid - 1] : 0);
    if (i < n) g_off[i] = excl;
    if (threadIdx.x == 1023) g_bsum[blockIdx.x] = excl + v;
}
__global__ void scanb_kernel(int nb) {
    if (threadIdx.x == 0 && blockIdx.x == 0) {
        int run = 0;
        for (int b = 0; b < nb; b++) { int t = g_bsum[b]; g_bsum[b] = run; run += t; }
        g_total = run;
    }
}
__global__ void finish_off_kernel(int n) {
    int i = blockIdx.x * 1024 + threadIdx.x;
    if (i < n) {
        int off = g_off[i] + g_bsum[i >> 10];
        g_off[i] = off;
        g_csrc[off] = i;
        g_cnt[i] = off + 1;
    }
    if (i == 0) g_off[n] = g_total;
}
__global__ void scatter_kernel(const int* __restrict__ ei, int E) {
    int i = blockIdx.x * blockDim.x + threadIdx.x;
    if (i >= E) return;
    int is64 = g_is64;
    int s = load_idx(ei, i, is64);
    int d = load_idx(ei, (long long)E + i, is64);
    int p = atomicAdd(&g_cnt[d], 1);
    g_csrc[p] = s;
}

// ---------------- W^T split: W[K][N] fp32 -> g_bth/g_btl [N][K] bf16 ----------
__global__ void wt_split_kernel(const float* __restrict__ W, int K, int N) {
    int i = blockIdx.x * blockDim.x + threadIdx.x;
    if (i >= N * K) return;
    int nn = i / K, kk = i - nn * K;
    float v = W[(size_t)kk * N + nn];
    __nv_bfloat16 h = __float2bfloat16(v);
    g_bth[i] = h;
    g_btl[i] = __float2bfloat16(v - __bfloat162float(h));
}

// ---- GEMM: block 128x128, 8 warps (2Mx4N), warp 64x32, mma.sync, hi/lo bf16 --
#define LDAB 48
#define OFF_AL 6144
#define OFF_BH 12288
#define OFF_BL 18432
#define STAGE_B 24576
#define SMEM_DYN (2 * STAGE_B)

template<typename TA>
__global__ __launch_bounds__(256, 2) void gemm_mma_kernel(
    const TA* __restrict__ A, int Kfull,
    const __nv_bfloat16* __restrict__ Bth, const __nv_bfloat16* __restrict__ Btl,
    __half* __restrict__ C,
    const float* __restrict__ avs, const float* __restrict__ avd,
    int M, int N)
{
    extern __shared__ __align__(16) char buf[];
    uint32_t sb = smem_u32(buf);

    int tid = threadIdx.x;
    int w = tid >> 5, lane = tid & 31;
    int wr = w >> 2, wc = w & 3;                 // warp tile 64(M) x 32(N)
    int r0 = blockIdx.x * 128, c0 = blockIdx.y * 128;

    float acc[4][4][4];
    #pragma unroll
    for (int mt = 0; mt < 4; mt++)
        #pragma unroll
        for (int nt = 0; nt < 4; nt++)
            #pragma unroll
            for (int q = 0; q < 4; q++) acc[mt][nt][q] = 0.f;

    int s_row = tid >> 1, s_half = (tid & 1) * 8;

    // ldmatrix lane offsets — A pattern (m16k16)
    int la_row = (lane & 15), la_k = (lane >> 4) * 8;
    uint32_t a_frag_off = (uint32_t)(la_row * LDAB + la_k * 2);
    // B pattern (n16k16)
    int lb_n = (lane & 7) + ((lane >> 4) & 1) * 8;
    int lb_k = ((lane >> 3) & 1) * 8;
    uint32_t b_frag_off = (uint32_t)(lb_n * LDAB + lb_k * 2);

    float arv[8];
    uint4 bh_rv, bl_rv;
    int steps = Kfull / 16;

    {   // prologue: k-step 0
        int gr = r0 + s_row;
        #pragma unroll
        for (int q = 0; q < 8; q++) arv[q] = 0.f;
        if (gr < M) load_a8(A + (size_t)gr * Kfull + s_half, arv);
        size_t bo = (size_t)(c0 + s_row) * Kfull + s_half;
        bh_rv = *(const uint4*)(Bth + bo);
        bl_rv = *(const uint4*)(Btl + bo);
    }
    {   // store stage 0
        char* st = buf;
        __nv_bfloat16 hs[8], ls[8];
        #pragma unroll
        for (int q = 0; q < 8; q++) {
            hs[q] = __float2bfloat16(arv[q]);
            ls[q] = __float2bfloat16(arv[q] - __bfloat162float(hs[q]));
        }
        *(uint4*)(st + s_row * LDAB + s_half * 2)          = *(uint4*)hs;
        *(uint4*)(st + OFF_AL + s_row * LDAB + s_half * 2) = *(uint4*)ls;
        *(uint4*)(st + OFF_BH + s_row * LDAB + s_half * 2) = bh_rv;
        *(uint4*)(st + OFF_BL + s_row * LDAB + s_half * 2) = bl_rv;
    }
    __syncthreads();

    for (int i = 0; i < steps; i++) {
        int cur = i & 1, nxt = cur ^ 1;
        if (i + 1 < steps) {
            int k0 = (i + 1) * 16;
            int gr = r0 + s_row;
            #pragma unroll
            for (int q = 0; q < 8; q++) arv[q] = 0.f;
            if (gr < M) load_a8(A + (size_t)gr * Kfull + k0 + s_half, arv);
            size_t bo = (size_t)(c0 + s_row) * Kfull + k0 + s_half;
            bh_rv = *(const uint4*)(Bth + bo);
            bl_rv = *(const uint4*)(Btl + bo);
        }
        {
            uint32_t st = sb + cur * STAGE_B;
            uint32_t bh[2][4], bl[2][4];
            #pragma unroll
            for (int np = 0; np < 2; np++) {
                uint32_t nbase = st + OFF_BH + (uint32_t)((wc * 32 + np * 16) * LDAB) + b_frag_off;
                ldsm4(bh[np], nbase);
                ldsm4(bl[np], nbase + (OFF_BL - OFF_BH));
            }
            #pragma unroll
            for (int mt = 0; mt < 4; mt++) {
                uint32_t ah[4], al[4];
                uint32_t rbase = st + (uint32_t)((wr * 64 + mt * 16) * LDAB) + a_frag_off;
                ldsm4(ah, rbase);
                ldsm4(al, rbase + OFF_AL);
                #pragma unroll
                for (int nt = 0; nt < 4; nt++) {
                    const uint32_t* bhp = &bh[nt >> 1][(nt & 1) * 2];
                    const uint32_t* blp = &bl[nt >> 1][(nt & 1) * 2];
                    mma16816(acc[mt][nt], ah, bhp);
                    mma16816(acc[mt][nt], ah, blp);
                    mma16816(acc[mt][nt], al, bhp);
                }
            }
        }
        if (i + 1 < steps) {
            char* st = buf + nxt * STAGE_B;
            __nv_bfloat16 hs[8], ls[8];
            #pragma unroll
            for (int q = 0; q < 8; q++) {
                hs[q] = __float2bfloat16(arv[q]);
                ls[q] = __float2bfloat16(arv[q] - __bfloat162float(hs[q]));
            }
            *(uint4*)(st + s_row * LDAB + s_half * 2)          = *(uint4*)hs;
            *(uint4*)(st + OFF_AL + s_row * LDAB + s_half * 2) = *(uint4*)ls;
            *(uint4*)(st + OFF_BH + s_row * LDAB + s_half * 2) = bh_rv;
            *(uint4*)(st + OFF_BL + s_row * LDAB + s_half * 2) = bl_rv;
        }
        __syncthreads();
    }

    // ---- store C (fp16) + fused alpha partials from fp32 accumulators ----
    {
        float as[4][2], ad[4][2];
        #pragma unroll
        for (int nt = 0; nt < 4; nt++) {
            int col = c0 + wc * 32 + nt * 8 + (lane & 3) * 2;
            as[nt][0] = avs[col];     as[nt][1] = avs[col + 1];
            ad[nt][0] = avd[col];     ad[nt][1] = avd[col + 1];
        }
        #pragma unroll
        for (int mt = 0; mt < 4; mt++) {
            int rA = r0 + wr * 64 + mt * 16 + (lane >> 2);
            int rB = rA + 8;
            float ssA = 0.f, sdA = 0.f, ssB = 0.f, sdB = 0.f;
            #pragma unroll
            for (int nt = 0; nt < 4; nt++) {
                float* c = acc[mt][nt];
                int col = c0 + wc * 32 + nt * 8 + (lane & 3) * 2;
                *(__half2*)(C + (size_t)rA * N + col) = __floats2half2_rn(c[0], c[1]);
                *(__half2*)(C + (size_t)rB * N + col) = __floats2half2_rn(c[2], c[3]);
                ssA += c[0] * as[nt][0] + c[1] * as[nt][1];
                sdA += c[0] * ad[nt][0] + c[1] * ad[nt][1];
                ssB += c[2] * as[nt][0] + c[3] * as[nt][1];
                sdB += c[2] * ad[nt][0] + c[3] * ad[nt][1];
            }
            #pragma unroll
            for (int o = 1; o < 4; o <<= 1) {
                ssA += __shfl_xor_sync(~0u, ssA, o);
                sdA += __shfl_xor_sync(~0u, sdA, o);
                ssB += __shfl_xor_sync(~0u, ssB, o);
                sdB += __shfl_xor_sync(~0u, sdB, o);
            }
            if ((lane & 3) == 0) {
                if (rA < M) { atomicAdd(&g_asrc[rA], ssA); atomicAdd(&g_adst[rA], sdA); }
                if (rB < M) { atomicAdd(&g_asrc[rB], ssB); atomicAdd(&g_adst[rB], sdB); }
            }
        }
    }
}

// ---------------- segment softmax: stats + normalized att per edge ----------
__global__ void stats_kernel(int n) {
    int w = (blockIdx.x * blockDim.x + threadIdx.x) >> 5;
    int lane = threadIdx.x & 31;
    if (w >= n) return;
    int beg = g_off[w], end = g_off[w + 1];
    float adi = g_adst[w];
    float mx = -1e30f, sm = 0.f;
    for (int k = beg + lane; k < end; k += 32) {
        int s = g_csrc[k];
        float e = g_asrc[s] + adi;
        e = e >= 0.f ? e : 0.2f * e;
        if (e > mx) { sm = sm * __expf(mx - e) + 1.f; mx = e; }
        else        { sm += __expf(e - mx); }
    }
    #pragma unroll
    for (int o = 16; o; o >>= 1) {
        float mo = __shfl_xor_sync(~0u, mx, o);
        float so = __shfl_xor_sync(~0u, sm, o);
        float nm = fmaxf(mx, mo);
        sm = sm * __expf(mx - nm) + so * __expf(mo - nm);
        mx = nm;
    }
    float inv = 1.f / sm;
    for (int k = beg + lane; k < end; k += 32) {
        int s = g_csrc[k];
        float e = g_asrc[s] + adi;
        e = e >= 0.f ? e : 0.2f * e;
        g_att[k] = __expf(e - mx) * inv;
    }
}

// ------- aggregation (warp per node, fp16 row gather, fp32 accumulate) -------
template<int F, bool RELU, typename OutT>
__global__ void agg_kernel(const __half* __restrict__ xw,
                           const float* __restrict__ bias,
                           OutT* __restrict__ out, int n)
{
    int w = (blockIdx.x * blockDim.x + threadIdx.x) >> 5;
    int lane = threadIdx.x & 31;
    if (w >= n) return;
    const int NV = F / 32;                      // halves per lane (8 or 4)
    int beg = g_off[w], end = g_off[w + 1];
    float acc[NV];
    #pragma unroll
    for (int q = 0; q < NV; q++) acc[q] = 0.f;

    int k = beg;
    for (; k + 2 <= end; k += 2) {
        int s0 = g_csrc[k], s1 = g_csrc[k + 1];
        float a0 = g_att[k], a1 = g_att[k + 1];
        const __half* r0p = xw + (size_t)s0 * F + lane * NV;
        const __half* r1p = xw + (size_t)s1 * F + lane * NV;
        if (NV == 8) {
            uint4 u0 = *(const uint4*)r0p;
            uint4 u1 = *(const uint4*)r1p;
            const __half2* h0 = (const __half2*)&u0;
            const __half2* h1 = (const __half2*)&u1;
            #pragma unroll
            for (int q = 0; q < 4; q++) {
                float2 f0 = __half22float2(h0[q]);
                float2 f1 = __half22float2(h1[q]);
                acc[2*q]   += a0 * f0.x + a1 * f1.x;
                acc[2*q+1] += a0 * f0.y + a1 * f1.y;
            }
        } else {
            uint2 u0 = *(const uint2*)r0p;
            uint2 u1 = *(const uint2*)r1p;
            const __half2* h0 = (const __half2*)&u0;
            const __half2* h1 = (const __half2*)&u1;
            #pragma unroll
            for (int q = 0; q < 2; q++) {
                float2 f0 = __half22float2(h0[q]);
                float2 f1 = __half22float2(h1[q]);
                acc[2*q]   += a0 * f0.x + a1 * f1.x;
                acc[2*q+1] += a0 * f0.y + a1 * f1.y;
            }
        }
    }
    if (k < end) {
        int s0 = g_csrc[k];
        float a0 = g_att[k];
        const __half* r0p = xw + (size_t)s0 * F + lane * NV;
        if (NV == 8) {
            uint4 u0 = *(const uint4*)r0p;
            const __half2* h0 = (const __half2*)&u0;
            #pragma unroll
            for (int q = 0; q < 4; q++) {
                float2 f0 = __half22float2(h0[q]);
                acc[2*q]   += a0 * f0.x;
                acc[2*q+1] += a0 * f0.y;
            }
        } else {
            uint2 u0 = *(const uint2*)r0p;
            const __half2* h0 = (const __half2*)&u0;
            #pragma unroll
            for (int q = 0; q < 2; q++) {
                float2 f0 = __half22float2(h0[q]);
                acc[2*q]   += a0 * f0.x;
                acc[2*q+1] += a0 * f0.y;
            }
        }
    }
    // bias + (relu) + store
    const float* bp = bias + lane * NV;
    #pragma unroll
    for (int q = 0; q < NV; q++) {
        float v = acc[q] + bp[q];
        if (RELU) v = fmaxf(v, 0.f);
        acc[q] = v;
    }
    if (sizeof(OutT) == 2) {
        __half* op = (__half*)out + (size_t)w * F + lane * NV;
        #pragma unroll
        for (int q = 0; q < NV; q += 2)
            *(__half2*)(op + q) = __floats2half2_rn(acc[q], acc[q+1]);
    } else {
        float* op = (float*)out + (size_t)w * F + lane * NV;
        #pragma unroll
        for (int q = 0; q < NV; q += 4)
            *(float4*)(op + q) = make_float4(acc[q], acc[q+1], acc[q+2], acc[q+3]);
    }
}

// ---------------- launch ----------------
extern "C" void kernel_launch(void* const* d_in, const int* in_sizes, int n_in,
                              void* d_out, int out_size) {
    const float* x   = (const float*)d_in[0];
    const int*   ei  = (const int*)d_in[1];
    const float* W1  = (const float*)d_in[2];
    const float* a1s = (const float*)d_in[3];
    const float* a1d = (const float*)d_in[4];
    const float* b1  = (const float*)d_in[5];
    const float* W2  = (const float*)d_in[6];
    const float* a2s = (const float*)d_in[7];
    const float* a2d = (const float*)d_in[8];
    const float* b2  = (const float*)d_in[9];
    float* out = (float*)d_out;

    int n = in_sizes[0] / 128;        // 50000
    int E = in_sizes[1] / 2;          // 800000

    __half *p_xwh = nullptr, *p_hh = nullptr;
    __nv_bfloat16 *p_bth = nullptr, *p_btl = nullptr;
    cudaGetSymbolAddress((void**)&p_xwh, g_xwh);
    cudaGetSymbolAddress((void**)&p_hh,  g_hh);
    cudaGetSymbolAddress((void**)&p_bth, g_bth);
    cudaGetSymbolAddress((void**)&p_btl, g_btl);

    cudaFuncSetAttribute(gemm_mma_kernel<float>,  cudaFuncAttributeMaxDynamicSharedMemorySize, SMEM_DYN);
    cudaFuncSetAttribute(gemm_mma_kernel<__half>, cudaFuncAttributeMaxDynamicSharedMemorySize, SMEM_DYN);

    int nblk    = (n + 255) / 256;
    int eblk    = (E + 255) / 256;
    int warpBlk = (n * 32 + 255) / 256;
    int sblk    = (n + 1023) / 1024;
    int rtiles  = (n + 127) / 128;    // 391
    dim3 g1(rtiles, 2);               // layer1: N=256
    dim3 g2(rtiles, 1);               // layer2: N=128

    // gemm1 lands in ncu's profiled slot (4th launch)
    detect_kernel<<<1, 32>>>(ei);
    init_kernel<<<nblk, 256>>>(n);
    wt_split_kernel<<<(128 * 256 + 255) / 256, 256>>>(W1, 128, 256);
    gemm_mma_kernel<float><<<g1, 256, SMEM_DYN>>>(x, 128, p_bth, p_btl, p_xwh, a1s, a1d, n, 256);
    hist_kernel<<<eblk, 256>>>(ei, E);
    blockscan_kernel<<<sblk, 1024>>>(n);
    scanb_kernel<<<1, 32>>>(sblk);
    finish_off_kernel<<<sblk, 1024>>>(n);
    scatter_kernel<<<eblk, 256>>>(ei, E);

    // ---- layer 1 tail ----
    stats_kernel<<<warpBlk, 256>>>(n);
    zero_alpha_kernel<<<nblk, 256>>>(n);
    agg_kernel<256, true, __half><<<warpBlk, 256>>>(p_xwh, b1, p_hh, n);

    // ---- layer 2 ----
    wt_split_kernel<<<(256 * 128 + 255) / 256, 256>>>(W2, 256, 128);
    gemm_mma_kernel<__half><<<g2, 256, SMEM_DYN>>>(p_hh, 256, p_bth, p_btl, p_xwh, a2s, a2d, n, 128);
    stats_kernel<<<warpBlk, 256>>>(n);
    agg_kernel<128, false, float><<<warpBlk, 256>>>(p_xwh, b2, out, n);
}

// round 13
// speedup vs baseline: 1.0771x; 1.0591x over previous
#include <cuda_runtime.h>
#include <cuda_bf16.h>
#include <cuda_fp16.h>
#include <math.h>
#include <stdint.h>

// ---------------- problem constants ----------------
#define MAXN 50000
#define NPAD 50048              // 391*128 padded rows (scratch only)
#define MAXE 800000
#define MAXTOT (MAXE + MAXN)

// ---------------- device scratch ----------------
__device__ __half g_xwh[(size_t)NPAD * 256]; // xw of current layer (fp16, gathered)
__device__ __half g_hh[(size_t)NPAD * 256];  // layer-1 output (fp16)
__device__ __half g_bth[32768];              // W^T hi  [N][K] fp16
__device__ __half g_btl[32768];              // W^T lo  [N][K] fp16
__device__ float g_asrc[MAXN];
__device__ float g_adst[MAXN];
__device__ float g_att[MAXTOT];
__device__ int   g_cnt[MAXN];
__device__ int   g_off[MAXN + 1];
__device__ int   g_csrc[MAXTOT];
__device__ int   g_bsum[64];
__device__ int   g_total;
__device__ int   g_is64;

// ---------------- mma / ldmatrix helpers ----------------
__device__ __forceinline__ uint32_t smem_u32(const void* p) {
    uint32_t a;
    asm("{ .reg .u64 t; cvta.to.shared.u64 t, %1; cvt.u32.u64 %0, t; }" : "=r"(a) : "l"(p));
    return a;
}
__device__ __forceinline__ void ldsm4(uint32_t* r, uint32_t addr) {
    asm volatile("ldmatrix.sync.aligned.m8n8.x4.shared.b16 {%0,%1,%2,%3}, [%4];"
        : "=r"(r[0]), "=r"(r[1]), "=r"(r[2]), "=r"(r[3]) : "r"(addr));
}
__device__ __forceinline__ void mma16816h(float* c, const uint32_t* a, const uint32_t* b) {
    asm volatile("mma.sync.aligned.m16n8k16.row.col.f32.f16.f16.f32 "
        "{%0,%1,%2,%3}, {%4,%5,%6,%7}, {%8,%9}, {%0,%1,%2,%3};"
        : "+f"(c[0]), "+f"(c[1]), "+f"(c[2]), "+f"(c[3])
        : "r"(a[0]), "r"(a[1]), "r"(a[2]), "r"(a[3]), "r"(b[0]), "r"(b[1]));
}

// 8-element A row loader -> fp32 (fp32 or fp16 source)
__device__ __forceinline__ void load_a8(const float* ap, float* v) {
    *(float4*)v       = *(const float4*)ap;
    *(float4*)(v + 4) = *(const float4*)(ap + 4);
}
__device__ __forceinline__ void load_a8(const __half* ap, float* v) {
    uint4 u = *(const uint4*)ap;
    const __half2* h = (const __half2*)&u;
    #pragma unroll
    for (int q = 0; q < 4; q++) {
        float2 f = __half22float2(h[q]);
        v[2*q] = f.x; v[2*q+1] = f.y;
    }
}

// ---------------- dtype detection ----------------
__global__ void detect_kernel(const int* __restrict__ ei) {
    if (threadIdx.x == 0 && blockIdx.x == 0) {
        int z = 1;
        #pragma unroll
        for (int i = 1; i < 64; i += 2)
            if (ei[i] != 0) z = 0;
        g_is64 = z;
    }
}
__device__ __forceinline__ int load_idx(const int* __restrict__ ei, long long elem, int is64) {
    return is64 ? ei[2 * elem] : ei[elem];
}

// ---------------- CSR build ----------------
__global__ void init_kernel(int n) {
    int i = blockIdx.x * blockDim.x + threadIdx.x;
    if (i < n) { g_cnt[i] = 1; g_asrc[i] = 0.f; g_adst[i] = 0.f; }
}
__global__ void zero_alpha_kernel(int n) {
    int i = blockIdx.x * blockDim.x + threadIdx.x;
    if (i < n) { g_asrc[i] = 0.f; g_adst[i] = 0.f; }
}
__global__ void hist_kernel(const int* __restrict__ ei, int E) {
    int i = blockIdx.x * blockDim.x + threadIdx.x;
    if (i >= E) return;
    int d = load_idx(ei, (long long)E + i, g_is64);
    atomicAdd(&g_cnt[d], 1);
}
__global__ __launch_bounds__(1024) void blockscan_kernel(int n) {
    __shared__ int warpsum[32];
    int i = blockIdx.x * 1024 + threadIdx.x;
    int v = (i < n) ? g_cnt[i] : 0;
    int lane = threadIdx.x & 31, wid = threadIdx.x >> 5;
    int s = v;
    #pragma unroll
    for (int o = 1; o < 32; o <<= 1) {
        int t = __shfl_up_sync(~0u, s, o);
        if (lane >= o) s += t;
    }
    if (lane == 31) warpsum[wid] = s;
    __syncthreads();
    if (wid == 0) {
        int ws = warpsum[lane];
        #pragma unroll
        for (int o = 1; o < 32; o <<= 1) {
            int t = __shfl_up_sync(~0u, ws, o);
            if (lane >= o) ws += t;
        }
        warpsum[lane] = ws;
    }
    __syncthreads();
    int excl = s - v + (wid ? warpsum[wid - 1] : 0);
    if (i < n) g_off[i] = excl;
    if (threadIdx.x == 1023) g_bsum[blockIdx.x] = excl + v;
}
__global__ void scanb_kernel(int nb) {
    if (threadIdx.x == 0 && blockIdx.x == 0) {
        int run = 0;
        for (int b = 0; b < nb; b++) { int t = g_bsum[b]; g_bsum[b] = run; run += t; }
        g_total = run;
    }
}
__global__ void finish_off_kernel(int n) {
    int i = blockIdx.x * 1024 + threadIdx.x;
    if (i < n) {
        int off = g_off[i] + g_bsum[i >> 10];
        g_off[i] = off;
        g_csrc[off] = i;
        g_cnt[i] = off + 1;
    }
    if (i == 0) g_off[n] = g_total;
}
__global__ void scatter_kernel(const int* __restrict__ ei, int E) {
    int i = blockIdx.x * blockDim.x + threadIdx.x;
    if (i >= E) return;
    int is64 = g_is64;
    int s = load_idx(ei, i, is64);
    int d = load_idx(ei, (long long)E + i, is64);
    int p = atomicAdd(&g_cnt[d], 1);
    g_csrc[p] = s;
}

// ------ W^T split: W[K][N] fp32 -> g_bth/g_btl [N][K] fp16 hi/lo -------------
__global__ void wt_split_kernel(const float* __restrict__ W, int K, int N) {
    int i = blockIdx.x * blockDim.x + threadIdx.x;
    if (i >= N * K) return;
    int nn = i / K, kk = i - nn * K;
    float v = W[(size_t)kk * N + nn];
    __half h = __float2half_rn(v);
    g_bth[i] = h;
    g_btl[i] = __float2half_rn(v - __half2float(h));
}

// ---- GEMM: block 128x128, 8 warps (2Mx4N), warp 64x32, fp16 mma, B hi/lo ----
// stage layout (bytes): A 128*48=6144 @0 | Bh 128*48 @6144 | Bl @12288 -> 18432
#define LDAB 48
#define OFF_BH 6144
#define OFF_BL 12288
#define STAGE_B 18432
#define SMEM_DYN (2 * STAGE_B)

template<typename TA>
__global__ __launch_bounds__(256, 2) void gemm_mma_kernel(
    const TA* __restrict__ A, int Kfull,
    const __half* __restrict__ Bth, const __half* __restrict__ Btl,
    __half* __restrict__ C,
    const float* __restrict__ avs, const float* __restrict__ avd,
    int M, int N)
{
    extern __shared__ __align__(16) char buf[];
    uint32_t sb = smem_u32(buf);

    int tid = threadIdx.x;
    int w = tid >> 5, lane = tid & 31;
    int wr = w >> 2, wc = w & 3;                 // warp tile 64(M) x 32(N)
    int r0 = blockIdx.x * 128, c0 = blockIdx.y * 128;

    float acc[4][4][4];
    #pragma unroll
    for (int mt = 0; mt < 4; mt++)
        #pragma unroll
        for (int nt = 0; nt < 4; nt++)
            #pragma unroll
            for (int q = 0; q < 4; q++) acc[mt][nt][q] = 0.f;

    int s_row = tid >> 1, s_half = (tid & 1) * 8;

    // ldmatrix lane offsets — A pattern (m16k16)
    int la_row = (lane & 15), la_k = (lane >> 4) * 8;
    uint32_t a_frag_off = (uint32_t)(la_row * LDAB + la_k * 2);
    // B pattern (n16k16)
    int lb_n = (lane & 7) + ((lane >> 4) & 1) * 8;
    int lb_k = ((lane >> 3) & 1) * 8;
    uint32_t b_frag_off = (uint32_t)(lb_n * LDAB + lb_k * 2);

    float arv[8];
    uint4 bh_rv, bl_rv;
    int steps = Kfull / 16;

    {   // prologue: k-step 0
        int gr = r0 + s_row;
        #pragma unroll
        for (int q = 0; q < 8; q++) arv[q] = 0.f;
        if (gr < M) load_a8(A + (size_t)gr * Kfull + s_half, arv);
        size_t bo = (size_t)(c0 + s_row) * Kfull + s_half;
        bh_rv = *(const uint4*)(Bth + bo);
        bl_rv = *(const uint4*)(Btl + bo);
    }
    {   // store stage 0
        char* st = buf;
        __half hs[8];
        #pragma unroll
        for (int q = 0; q < 8; q++) hs[q] = __float2half_rn(arv[q]);
        *(uint4*)(st + s_row * LDAB + s_half * 2)          = *(uint4*)hs;
        *(uint4*)(st + OFF_BH + s_row * LDAB + s_half * 2) = bh_rv;
        *(uint4*)(st + OFF_BL + s_row * LDAB + s_half * 2) = bl_rv;
    }
    __syncthreads();

    for (int i = 0; i < steps; i++) {
        int cur = i & 1, nxt = cur ^ 1;
        if (i + 1 < steps) {   // register prefetch of next k-step
            int k0 = (i + 1) * 16;
            int gr = r0 + s_row;
            #pragma unroll
            for (int q = 0; q < 8; q++) arv[q] = 0.f;
            if (gr < M) load_a8(A + (size_t)gr * Kfull + k0 + s_half, arv);
            size_t bo = (size_t)(c0 + s_row) * Kfull + k0 + s_half;
            bh_rv = *(const uint4*)(Bth + bo);
            bl_rv = *(const uint4*)(Btl + bo);
        }
        {   // compute on current stage: 2-term fp16 MMA
            uint32_t st = sb + cur * STAGE_B;
            uint32_t bh[2][4], bl[2][4];
            #pragma unroll
            for (int np = 0; np < 2; np++) {
                uint32_t nbase = st + OFF_BH + (uint32_t)((wc * 32 + np * 16) * LDAB) + b_frag_off;
                ldsm4(bh[np], nbase);
                ldsm4(bl[np], nbase + (OFF_BL - OFF_BH));
            }
            #pragma unroll
            for (int mt = 0; mt < 4; mt++) {
                uint32_t af[4];
                uint32_t rbase = st + (uint32_t)((wr * 64 + mt * 16) * LDAB) + a_frag_off;
                ldsm4(af, rbase);
                #pragma unroll
                for (int nt = 0; nt < 4; nt++) {
                    const uint32_t* bhp = &bh[nt >> 1][(nt & 1) * 2];
                    const uint32_t* blp = &bl[nt >> 1][(nt & 1) * 2];
                    mma16816h(acc[mt][nt], af, bhp);
                    mma16816h(acc[mt][nt], af, blp);
                }
            }
        }
        if (i + 1 < steps) {   // commit prefetched k-step
            char* st = buf + nxt * STAGE_B;
            __half hs[8];
            #pragma unroll
            for (int q = 0; q < 8; q++) hs[q] = __float2half_rn(arv[q]);
            *(uint4*)(st + s_row * LDAB + s_half * 2)          = *(uint4*)hs;
            *(uint4*)(st + OFF_BH + s_row * LDAB + s_half * 2) = bh_rv;
            *(uint4*)(st + OFF_BL + s_row * LDAB + s_half * 2) = bl_rv;
        }
        __syncthreads();
    }

    // ---- store C (fp16) + fused alpha partials from fp32 accumulators ----
    {
        float as[4][2], ad[4][2];
        #pragma unroll
        for (int nt = 0; nt < 4; nt++) {
            int col = c0 + wc * 32 + nt * 8 + (lane & 3) * 2;
            as[nt][0] = avs[col];     as[nt][1] = avs[col + 1];
            ad[nt][0] = avd[col];     ad[nt][1] = avd[col + 1];
        }
        #pragma unroll
        for (int mt = 0; mt < 4; mt++) {
            int rA = r0 + wr * 64 + mt * 16 + (lane >> 2);
            int rB = rA + 8;
            float ssA = 0.f, sdA = 0.f, ssB = 0.f, sdB = 0.f;
            #pragma unroll
            for (int nt = 0; nt < 4; nt++) {
                float* c = acc[mt][nt];
                int col = c0 + wc * 32 + nt * 8 + (lane & 3) * 2;
                *(__half2*)(C + (size_t)rA * N + col) = __floats2half2_rn(c[0], c[1]);
                *(__half2*)(C + (size_t)rB * N + col) = __floats2half2_rn(c[2], c[3]);
                ssA += c[0] * as[nt][0] + c[1] * as[nt][1];
                sdA += c[0] * ad[nt][0] + c[1] * ad[nt][1];
                ssB += c[2] * as[nt][0] + c[3] * as[nt][1];
                sdB += c[2] * ad[nt][0] + c[3] * ad[nt][1];
            }
            #pragma unroll
            for (int o = 1; o < 4; o <<= 1) {
                ssA += __shfl_xor_sync(~0u, ssA, o);
                sdA += __shfl_xor_sync(~0u, sdA, o);
                ssB += __shfl_xor_sync(~0u, ssB, o);
                sdB += __shfl_xor_sync(~0u, sdB, o);
            }
            if ((lane & 3) == 0) {
                if (rA < M) { atomicAdd(&g_asrc[rA], ssA); atomicAdd(&g_adst[rA], sdA); }
                if (rB < M) { atomicAdd(&g_asrc[rB], ssB); atomicAdd(&g_adst[rB], sdB); }
            }
        }
    }
}

// ---------------- segment softmax: stats + normalized att per edge ----------
__global__ void stats_kernel(int n) {
    int w = (blockIdx.x * blockDim.x + threadIdx.x) >> 5;
    int lane = threadIdx.x & 31;
    if (w >= n) return;
    int beg = g_off[w], end = g_off[w + 1];
    float adi = g_adst[w];
    float mx = -1e30f, sm = 0.f;
    for (int k = beg + lane; k < end; k += 32) {
        int s = g_csrc[k];
        float e = g_asrc[s] + adi;
        e = e >= 0.f ? e : 0.2f * e;
        if (e > mx) { sm = sm * __expf(mx - e) + 1.f; mx = e; }
        else        { sm += __expf(e - mx); }
    }
    #pragma unroll
    for (int o = 16; o; o >>= 1) {
        float mo = __shfl_xor_sync(~0u, mx, o);
        float so = __shfl_xor_sync(~0u, sm, o);
        float nm = fmaxf(mx, mo);
        sm = sm * __expf(mx - nm) + so * __expf(mo - nm);
        mx = nm;
    }
    float inv = 1.f / sm;
    for (int k = beg + lane; k < end; k += 32) {
        int s = g_csrc[k];
        float e = g_asrc[s] + adi;
        e = e >= 0.f ? e : 0.2f * e;
        g_att[k] = __expf(e - mx) * inv;
    }
}

// ------- aggregation (warp per node, fp16 row gather, fp32 accumulate) -------
template<int F, bool RELU, typename OutT>
__global__ void agg_kernel(const __half* __restrict__ xw,
                           const float* __restrict__ bias,
                           OutT* __restrict__ out, int n)
{
    int w = (blockIdx.x * blockDim.x + threadIdx.x) >> 5;
    int lane = threadIdx.x & 31;
    if (w >= n) return;
    const int NV = F / 32;                      // halves per lane (8 or 4)
    int beg = g_off[w], end = g_off[w + 1];
    float acc[NV];
    #pragma unroll
    for (int q = 0; q < NV; q++) acc[q] = 0.f;

    int k = beg;
    for (; k + 2 <= end; k += 2) {
        int s0 = g_csrc[k], s1 = g_csrc[k + 1];
        float a0 = g_att[k], a1 = g_att[k + 1];
        const __half* r0p = xw + (size_t)s0 * F + lane * NV;
        const __half* r1p = xw + (size_t)s1 * F + lane * NV;
        if (NV == 8) {
            uint4 u0 = *(const uint4*)r0p;
            uint4 u1 = *(const uint4*)r1p;
            const __half2* h0 = (const __half2*)&u0;
            const __half2* h1 = (const __half2*)&u1;
            #pragma unroll
            for (int q = 0; q < 4; q++) {
                float2 f0 = __half22float2(h0[q]);
                float2 f1 = __half22float2(h1[q]);
                acc[2*q]   += a0 * f0.x + a1 * f1.x;
                acc[2*q+1] += a0 * f0.y + a1 * f1.y;
            }
        } else {
            uint2 u0 = *(const uint2*)r0p;
            uint2 u1 = *(const uint2*)r1p;
            const __half2* h0 = (const __half2*)&u0;
            const __half2* h1 = (const __half2*)&u1;
            #pragma unroll
            for (int q = 0; q < 2; q++) {
                float2 f0 = __half22float2(h0[q]);
                float2 f1 = __half22float2(h1[q]);
                acc[2*q]   += a0 * f0.x + a1 * f1.x;
                acc[2*q+1] += a0 * f0.y + a1 * f1.y;
            }
        }
    }
    if (k < end) {
        int s0 = g_csrc[k];
        float a0 = g_att[k];
        const __half* r0p = xw + (size_t)s0 * F + lane * NV;
        if (NV == 8) {
            uint4 u0 = *(const uint4*)r0p;
            const __half2* h0 = (const __half2*)&u0;
            #pragma unroll
            for (int q = 0; q < 4; q++) {
                float2 f0 = __half22float2(h0[q]);
                acc[2*q]   += a0 * f0.x;
                acc[2*q+1] += a0 * f0.y;
            }
        } else {
            uint2 u0 = *(const uint2*)r0p;
            const __half2* h0 = (const __half2*)&u0;
            #pragma unroll
            for (int q = 0; q < 2; q++) {
                float2 f0 = __half22float2(h0[q]);
                acc[2*q]   += a0 * f0.x;
                acc[2*q+1] += a0 * f0.y;
            }
        }
    }
    // bias + (relu) + store
    const float* bp = bias + lane * NV;
    #pragma unroll
    for (int q = 0; q < NV; q++) {
        float v = acc[q] + bp[q];
        if (RELU) v = fmaxf(v, 0.f);
        acc[q] = v;
    }
    if (sizeof(OutT) == 2) {
        __half* op = (__half*)out + (size_t)w * F + lane * NV;
        #pragma unroll
        for (int q = 0; q < NV; q += 2)
            *(__half2*)(op + q) = __floats2half2_rn(acc[q], acc[q+1]);
    } else {
        float* op = (float*)out + (size_t)w * F + lane * NV;
        #pragma unroll
        for (int q = 0; q < NV; q += 4)
            *(float4*)(op + q) = make_float4(acc[q], acc[q+1], acc[q+2], acc[q+3]);
    }
}

// ---------------- launch ----------------
extern "C" void kernel_launch(void* const* d_in, const int* in_sizes, int n_in,
                              void* d_out, int out_size) {
    const float* x   = (const float*)d_in[0];
    const int*   ei  = (const int*)d_in[1];
    const float* W1  = (const float*)d_in[2];
    const float* a1s = (const float*)d_in[3];
    const float* a1d = (const float*)d_in[4];
    const float* b1  = (const float*)d_in[5];
    const float* W2  = (const float*)d_in[6];
    const float* a2s = (const float*)d_in[7];
    const float* a2d = (const float*)d_in[8];
    const float* b2  = (const float*)d_in[9];
    float* out = (float*)d_out;

    int n = in_sizes[0] / 128;        // 50000
    int E = in_sizes[1] / 2;          // 800000

    __half *p_xwh = nullptr, *p_hh = nullptr, *p_bth = nullptr, *p_btl = nullptr;
    cudaGetSymbolAddress((void**)&p_xwh, g_xwh);
    cudaGetSymbolAddress((void**)&p_hh,  g_hh);
    cudaGetSymbolAddress((void**)&p_bth, g_bth);
    cudaGetSymbolAddress((void**)&p_btl, g_btl);

    cudaFuncSetAttribute(gemm_mma_kernel<float>,  cudaFuncAttributeMaxDynamicSharedMemorySize, SMEM_DYN);
    cudaFuncSetAttribute(gemm_mma_kernel<__half>, cudaFuncAttributeMaxDynamicSharedMemorySize, SMEM_DYN);

    int nblk    = (n + 255) / 256;
    int eblk    = (E + 255) / 256;
    int warpBlk = (n * 32 + 255) / 256;
    int sblk    = (n + 1023) / 1024;
    int rtiles  = (n + 127) / 128;    // 391
    dim3 g1(rtiles, 2);               // layer1: N=256
    dim3 g2(rtiles, 1);               // layer2: N=128

    // gemm1 lands in ncu's profiled slot (4th launch)
    detect_kernel<<<1, 32>>>(ei);
    init_kernel<<<nblk, 256>>>(n);
    wt_split_kernel<<<(128 * 256 + 255) / 256, 256>>>(W1, 128, 256);
    gemm_mma_kernel<float><<<g1, 256, SMEM_DYN>>>(x, 128, p_bth, p_btl, p_xwh, a1s, a1d, n, 256);
    hist_kernel<<<eblk, 256>>>(ei, E);
    blockscan_kernel<<<sblk, 1024>>>(n);
    scanb_kernel<<<1, 32>>>(sblk);
    finish_off_kernel<<<sblk, 1024>>>(n);
    scatter_kernel<<<eblk, 256>>>(ei, E);

    // ---- layer 1 tail ----
    stats_kernel<<<warpBlk, 256>>>(n);
    zero_alpha_kernel<<<nblk, 256>>>(n);
    agg_kernel<256, true, __half><<<warpBlk, 256>>>(p_xwh, b1, p_hh, n);

    // ---- layer 2 ----
    wt_split_kernel<<<(256 * 128 + 255) / 256, 256>>>(W2, 256, 128);
    gemm_mma_kernel<__half><<<g2, 256, SMEM_DYN>>>(p_hh, 256, p_bth, p_btl, p_xwh, a2s, a2d, n, 128);
    stats_kernel<<<warpBlk, 256>>>(n);
    agg_kernel<128, false, float><<<warpBlk, 256>>>(p_xwh, b2, out, n);
}

// round 14
// speedup vs baseline: 1.1474x; 1.0653x over previous
#include <cuda_runtime.h>
#include <cuda_fp16.h>
#include <math.h>
#include <stdint.h>

// ---------------- problem constants ----------------
#define MAXN 50000
#define NPAD 50048              // 391*128 padded rows (scratch only)
#define MAXE 800000
#define MAXTOT (MAXE + MAXN)

// ---------------- device scratch ----------------
__device__ __half g_xh[(size_t)NPAD * 128];  // x converted to fp16
__device__ __half g_xwh[(size_t)NPAD * 256]; // xw of current layer (fp16, gathered)
__device__ __half g_hh[(size_t)NPAD * 256];  // layer-1 output (fp16)
__device__ __half g_bth[32768];              // W^T hi  [N][K] fp16
__device__ __half g_btl[32768];              // W^T lo  [N][K] fp16
__device__ float g_asrc[MAXN];
__device__ float g_adst[MAXN];
__device__ float g_att[MAXTOT];
__device__ int   g_cnt[MAXN];
__device__ int   g_off[MAXN + 1];
__device__ int   g_csrc[MAXTOT];
__device__ int   g_bsum[64];
__device__ int   g_total;
__device__ int   g_is64;

// ---------------- mma / ldmatrix / cp.async helpers ----------------
__device__ __forceinline__ uint32_t smem_u32(const void* p) {
    uint32_t a;
    asm("{ .reg .u64 t; cvta.to.shared.u64 t, %1; cvt.u32.u64 %0, t; }" : "=r"(a) : "l"(p));
    return a;
}
__device__ __forceinline__ void ldsm4(uint32_t* r, uint32_t addr) {
    asm volatile("ldmatrix.sync.aligned.m8n8.x4.shared.b16 {%0,%1,%2,%3}, [%4];"
        : "=r"(r[0]), "=r"(r[1]), "=r"(r[2]), "=r"(r[3]) : "r"(addr));
}
__device__ __forceinline__ void mma16816h(float* c, const uint32_t* a, const uint32_t* b) {
    asm volatile("mma.sync.aligned.m16n8k16.row.col.f32.f16.f16.f32 "
        "{%0,%1,%2,%3}, {%4,%5,%6,%7}, {%8,%9}, {%0,%1,%2,%3};"
        : "+f"(c[0]), "+f"(c[1]), "+f"(c[2]), "+f"(c[3])
        : "r"(a[0]), "r"(a[1]), "r"(a[2]), "r"(a[3]), "r"(b[0]), "r"(b[1]));
}
__device__ __forceinline__ void cp16(uint32_t dst, const void* src) {
    asm volatile("cp.async.cg.shared.global [%0], [%1], 16;" :: "r"(dst), "l"(src));
}
#define CP_COMMIT() asm volatile("cp.async.commit_group;" ::: "memory")
#define CP_WAIT0()  asm volatile("cp.async.wait_group 0;" ::: "memory")

// ---------------- dtype detection + init (merged) ----------------
__global__ void initdet_kernel(const int* __restrict__ ei, int n) {
    int i = blockIdx.x * blockDim.x + threadIdx.x;
    if (i == 0) {
        int z = 1;
        #pragma unroll
        for (int q = 1; q < 64; q += 2)
            if (ei[q] != 0) z = 0;
        g_is64 = z;
    }
    if (i < n) { g_cnt[i] = 1; g_asrc[i] = 0.f; g_adst[i] = 0.f; }
}
__device__ __forceinline__ int load_idx(const int* __restrict__ ei, long long elem, int is64) {
    return is64 ? ei[2 * elem] : ei[elem];
}

// ---------------- x fp32 -> fp16 ----------------
__global__ void x2h_kernel(const float* __restrict__ x, int n8) {
    int i = blockIdx.x * blockDim.x + threadIdx.x;
    if (i >= n8) return;
    float4 v0 = ((const float4*)x)[2 * i];
    float4 v1 = ((const float4*)x)[2 * i + 1];
    __half hs[8] = {__float2half_rn(v0.x), __float2half_rn(v0.y),
                    __float2half_rn(v0.z), __float2half_rn(v0.w),
                    __float2half_rn(v1.x), __float2half_rn(v1.y),
                    __float2half_rn(v1.z), __float2half_rn(v1.w)};
    ((uint4*)g_xh)[i] = *(uint4*)hs;
}

// ---------------- CSR build ----------------
__global__ void zero_alpha_kernel(int n) {
    int i = blockIdx.x * blockDim.x + threadIdx.x;
    if (i < n) { g_asrc[i] = 0.f; g_adst[i] = 0.f; }
}
__global__ void hist_kernel(const int* __restrict__ ei, int E) {
    int i = blockIdx.x * blockDim.x + threadIdx.x;
    if (i >= E) return;
    int d = load_idx(ei, (long long)E + i, g_is64);
    atomicAdd(&g_cnt[d], 1);
}
__global__ __launch_bounds__(1024) void blockscan_kernel(int n) {
    __shared__ int warpsum[32];
    int i = blockIdx.x * 1024 + threadIdx.x;
    int v = (i < n) ? g_cnt[i] : 0;
    int lane = threadIdx.x & 31, wid = threadIdx.x >> 5;
    int s = v;
    #pragma unroll
    for (int o = 1; o < 32; o <<= 1) {
        int t = __shfl_up_sync(~0u, s, o);
        if (lane >= o) s += t;
    }
    if (lane == 31) warpsum[wid] = s;
    __syncthreads();
    if (wid == 0) {
        int ws = warpsum[lane];
        #pragma unroll
        for (int o = 1; o < 32; o <<= 1) {
            int t = __shfl_up_sync(~0u, ws, o);
            if (lane >= o) ws += t;
        }
        warpsum[lane] = ws;
    }
    __syncthreads();
    int excl = s - v + (wid ? warpsum[wid - 1] : 0);
    if (i < n) g_off[i] = excl;
    if (threadIdx.x == 1023) g_bsum[blockIdx.x] = excl + v;
}
__global__ void scanb_kernel(int nb) {
    if (threadIdx.x == 0 && blockIdx.x == 0) {
        int run = 0;
        for (int b = 0; b < nb; b++) { int t = g_bsum[b]; g_bsum[b] = run; run += t; }
        g_total = run;
    }
}
__global__ void finish_off_kernel(int n) {
    int i = blockIdx.x * 1024 + threadIdx.x;
    if (i < n) {
        int off = g_off[i] + g_bsum[i >> 10];
        g_off[i] = off;
        g_csrc[off] = i;
        g_cnt[i] = off + 1;
    }
    if (i == 0) g_off[n] = g_total;
}
__global__ void scatter_kernel(const int* __restrict__ ei, int E) {
    int i = blockIdx.x * blockDim.x + threadIdx.x;
    if (i >= E) return;
    int is64 = g_is64;
    int s = load_idx(ei, i, is64);
    int d = load_idx(ei, (long long)E + i, is64);
    int p = atomicAdd(&g_cnt[d], 1);
    g_csrc[p] = s;
}

// ------ W^T split: W[K][N] fp32 -> g_bth/g_btl [N][K] fp16 hi/lo -------------
__global__ void wt_split_kernel(const float* __restrict__ W, int K, int N) {
    int i = blockIdx.x * blockDim.x + threadIdx.x;
    if (i >= N * K) return;
    int nn = i / K, kk = i - nn * K;
    float v = W[(size_t)kk * N + nn];
    __half h = __float2half_rn(v);
    g_bth[i] = h;
    g_btl[i] = __float2half_rn(v - __half2float(h));
}

// ---- GEMM: block 128x128, 8 warps (2Mx4N), warp 64x32, fp16 mma, cp.async ---
// k-step 32. Stage (80B-pitch rows): A 128*80 @0 | Bh @10240 | Bl @20480 -> 30720
#define LDP 80
#define OFF_BH 10240
#define OFF_BL 20480
#define STAGE_B 30720
#define SMEM_DYN (2 * STAGE_B)

__global__ __launch_bounds__(256, 2) void gemm_mma_kernel(
    const __half* __restrict__ A, int Kfull,
    const __half* __restrict__ Bth, const __half* __restrict__ Btl,
    __half* __restrict__ C,
    const float* __restrict__ avs, const float* __restrict__ avd,
    int M, int N)
{
    extern __shared__ __align__(16) char buf[];
    uint32_t sb = smem_u32(buf);

    int tid = threadIdx.x;
    int w = tid >> 5, lane = tid & 31;
    int wr = w >> 2, wc = w & 3;                 // warp tile 64(M) x 32(N)
    int r0 = blockIdx.x * 128, c0 = blockIdx.y * 128;

    float acc[4][4][4];
    #pragma unroll
    for (int mt = 0; mt < 4; mt++)
        #pragma unroll
        for (int nt = 0; nt < 4; nt++)
            #pragma unroll
            for (int q = 0; q < 4; q++) acc[mt][nt][q] = 0.f;

    // ldmatrix lane offsets — A pattern (m16k16)
    int la_row = (lane & 15), la_k = (lane >> 4) * 8;
    uint32_t a_frag_off = (uint32_t)(la_row * LDP + la_k * 2);
    // B pattern (n16k16)
    int lb_n = (lane & 7) + ((lane >> 4) & 1) * 8;
    int lb_k = ((lane >> 3) & 1) * 8;
    uint32_t b_frag_off = (uint32_t)(lb_n * LDP + lb_k * 2);

    int steps = Kfull / 32;

    // stage loader: 512 16B-chunks per matrix, 2 per thread per matrix
    auto stage_load = [&](uint32_t st, int k0) {
        #pragma unroll
        for (int j = 0; j < 2; j++) {
            int c = tid + 256 * j;
            int row = c >> 2, col = (c & 3) * 8;   // col in halves
            uint32_t doff = (uint32_t)(row * LDP + col * 2);
            cp16(st + doff,          A   + (size_t)(r0 + row) * Kfull + k0 + col);
            size_t bo = (size_t)(c0 + row) * Kfull + k0 + col;
            cp16(st + OFF_BH + doff, Bth + bo);
            cp16(st + OFF_BL + doff, Btl + bo);
        }
        CP_COMMIT();
    };

    stage_load(sb, 0);
    CP_WAIT0();
    __syncthreads();

    for (int i = 0; i < steps; i++) {
        uint32_t st  = sb + (uint32_t)(i & 1) * STAGE_B;
        if (i + 1 < steps) stage_load(sb + (uint32_t)((i + 1) & 1) * STAGE_B, (i + 1) * 32);
        // compute on current stage: 2 k16 sub-steps
        #pragma unroll
        for (int ks = 0; ks < 2; ks++) {
            uint32_t koff = (uint32_t)(ks * 32);   // 16 halves = 32 bytes
            uint32_t bh[2][4], bl[2][4];
            #pragma unroll
            for (int np = 0; np < 2; np++) {
                uint32_t nbase = st + OFF_BH + (uint32_t)((wc * 32 + np * 16) * LDP) + b_frag_off + koff;
                ldsm4(bh[np], nbase);
                ldsm4(bl[np], nbase + (OFF_BL - OFF_BH));
            }
            #pragma unroll
            for (int mt = 0; mt < 4; mt++) {
                uint32_t af[4];
                ldsm4(af, st + (uint32_t)((wr * 64 + mt * 16) * LDP) + a_frag_off + koff);
                #pragma unroll
                for (int nt = 0; nt < 4; nt++) {
                    const uint32_t* bhp = &bh[nt >> 1][(nt & 1) * 2];
                    const uint32_t* blp = &bl[nt >> 1][(nt & 1) * 2];
                    mma16816h(acc[mt][nt], af, bhp);
                    mma16816h(acc[mt][nt], af, blp);
                }
            }
        }
        CP_WAIT0();
        __syncthreads();
    }

    // ---- store C (fp16) + fused alpha partials from fp32 accumulators ----
    {
        float as[4][2], ad[4][2];
        #pragma unroll
        for (int nt = 0; nt < 4; nt++) {
            int col = c0 + wc * 32 + nt * 8 + (lane & 3) * 2;
            as[nt][0] = avs[col];     as[nt][1] = avs[col + 1];
            ad[nt][0] = avd[col];     ad[nt][1] = avd[col + 1];
        }
        #pragma unroll
        for (int mt = 0; mt < 4; mt++) {
            int rA = r0 + wr * 64 + mt * 16 + (lane >> 2);
            int rB = rA + 8;
            float ssA = 0.f, sdA = 0.f, ssB = 0.f, sdB = 0.f;
            #pragma unroll
            for (int nt = 0; nt < 4; nt++) {
                float* c = acc[mt][nt];
                int col = c0 + wc * 32 + nt * 8 + (lane & 3) * 2;
                *(__half2*)(C + (size_t)rA * N + col) = __floats2half2_rn(c[0], c[1]);
                *(__half2*)(C + (size_t)rB * N + col) = __floats2half2_rn(c[2], c[3]);
                ssA += c[0] * as[nt][0] + c[1] * as[nt][1];
                sdA += c[0] * ad[nt][0] + c[1] * ad[nt][1];
                ssB += c[2] * as[nt][0] + c[3] * as[nt][1];
                sdB += c[2] * ad[nt][0] + c[3] * ad[nt][1];
            }
            #pragma unroll
            for (int o = 1; o < 4; o <<= 1) {
                ssA += __shfl_xor_sync(~0u, ssA, o);
                sdA += __shfl_xor_sync(~0u, sdA, o);
                ssB += __shfl_xor_sync(~0u, ssB, o);
                sdB += __shfl_xor_sync(~0u, sdB, o);
            }
            if ((lane & 3) == 0) {
                if (rA < M) { atomicAdd(&g_asrc[rA], ssA); atomicAdd(&g_adst[rA], sdA); }
                if (rB < M) { atomicAdd(&g_asrc[rB], ssB); atomicAdd(&g_adst[rB], sdB); }
            }
        }
    }
}

// ---------------- segment softmax: stats + normalized att per edge ----------
__global__ void stats_kernel(int n) {
    int w = (blockIdx.x * blockDim.x + threadIdx.x) >> 5;
    int lane = threadIdx.x & 31;
    if (w >= n) return;
    int beg = g_off[w], end = g_off[w + 1];
    float adi = g_adst[w];
    float mx = -1e30f, sm = 0.f;
    for (int k = beg + lane; k < end; k += 32) {
        int s = g_csrc[k];
        float e = g_asrc[s] + adi;
        e = e >= 0.f ? e : 0.2f * e;
        if (e > mx) { sm = sm * __expf(mx - e) + 1.f; mx = e; }
        else        { sm += __expf(e - mx); }
    }
    #pragma unroll
    for (int o = 16; o; o >>= 1) {
        float mo = __shfl_xor_sync(~0u, mx, o);
        float so = __shfl_xor_sync(~0u, sm, o);
        float nm = fmaxf(mx, mo);
        sm = sm * __expf(mx - nm) + so * __expf(mo - nm);
        mx = nm;
    }
    float inv = 1.f / sm;
    for (int k = beg + lane; k < end; k += 32) {
        int s = g_csrc[k];
        float e = g_asrc[s] + adi;
        e = e >= 0.f ? e : 0.2f * e;
        g_att[k] = __expf(e - mx) * inv;
    }
}

// ------- aggregation (warp per node, fp16 row gather, fp32 accumulate) -------
template<int F, bool RELU, typename OutT>
__global__ void agg_kernel(const __half* __restrict__ xw,
                           const float* __restrict__ bias,
                           OutT* __restrict__ out, int n)
{
    int w = (blockIdx.x * blockDim.x + threadIdx.x) >> 5;
    int lane = threadIdx.x & 31;
    if (w >= n) return;
    const int NV = F / 32;                      // halves per lane (8 or 4)
    int beg = g_off[w], end = g_off[w + 1];
    float acc[NV];
    #pragma unroll
    for (int q = 0; q < NV; q++) acc[q] = 0.f;

    int k = beg;
    for (; k + 2 <= end; k += 2) {
        int s0 = g_csrc[k], s1 = g_csrc[k + 1];
        float a0 = g_att[k], a1 = g_att[k + 1];
        const __half* r0p = xw + (size_t)s0 * F + lane * NV;
        const __half* r1p = xw + (size_t)s1 * F + lane * NV;
        if (NV == 8) {
            uint4 u0 = *(const uint4*)r0p;
            uint4 u1 = *(const uint4*)r1p;
            const __half2* h0 = (const __half2*)&u0;
            const __half2* h1 = (const __half2*)&u1;
            #pragma unroll
            for (int q = 0; q < 4; q++) {
                float2 f0 = __half22float2(h0[q]);
                float2 f1 = __half22float2(h1[q]);
                acc[2*q]   += a0 * f0.x + a1 * f1.x;
                acc[2*q+1] += a0 * f0.y + a1 * f1.y;
            }
        } else {
            uint2 u0 = *(const uint2*)r0p;
            uint2 u1 = *(const uint2*)r1p;
            const __half2* h0 = (const __half2*)&u0;
            const __half2* h1 = (const __half2*)&u1;
            #pragma unroll
            for (int q = 0; q < 2; q++) {
                float2 f0 = __half22float2(h0[q]);
                float2 f1 = __half22float2(h1[q]);
                acc[2*q]   += a0 * f0.x + a1 * f1.x;
                acc[2*q+1] += a0 * f0.y + a1 * f1.y;
            }
        }
    }
    if (k < end) {
        int s0 = g_csrc[k];
        float a0 = g_att[k];
        const __half* r0p = xw + (size_t)s0 * F + lane * NV;
        if (NV == 8) {
            uint4 u0 = *(const uint4*)r0p;
            const __half2* h0 = (const __half2*)&u0;
            #pragma unroll
            for (int q = 0; q < 4; q++) {
                float2 f0 = __half22float2(h0[q]);
                acc[2*q]   += a0 * f0.x;
                acc[2*q+1] += a0 * f0.y;
            }
        } else {
            uint2 u0 = *(const uint2*)r0p;
            const __half2* h0 = (const __half2*)&u0;
            #pragma unroll
            for (int q = 0; q < 2; q++) {
                float2 f0 = __half22float2(h0[q]);
                acc[2*q]   += a0 * f0.x;
                acc[2*q+1] += a0 * f0.y;
            }
        }
    }
    // bias + (relu) + store
    const float* bp = bias + lane * NV;
    #pragma unroll
    for (int q = 0; q < NV; q++) {
        float v = acc[q] + bp[q];
        if (RELU) v = fmaxf(v, 0.f);
        acc[q] = v;
    }
    if (sizeof(OutT) == 2) {
        __half* op = (__half*)out + (size_t)w * F + lane * NV;
        #pragma unroll
        for (int q = 0; q < NV; q += 2)
            *(__half2*)(op + q) = __floats2half2_rn(acc[q], acc[q+1]);
    } else {
        float* op = (float*)out + (size_t)w * F + lane * NV;
        #pragma unroll
        for (int q = 0; q < NV; q += 4)
            *(float4*)(op + q) = make_float4(acc[q], acc[q+1], acc[q+2], acc[q+3]);
    }
}

// ---------------- launch ----------------
extern "C" void kernel_launch(void* const* d_in, const int* in_sizes, int n_in,
                              void* d_out, int out_size) {
    const float* x   = (const float*)d_in[0];
    const int*   ei  = (const int*)d_in[1];
    const float* W1  = (const float*)d_in[2];
    const float* a1s = (const float*)d_in[3];
    const float* a1d = (const float*)d_in[4];
    const float* b1  = (const float*)d_in[5];
    const float* W2  = (const float*)d_in[6];
    const float* a2s = (const float*)d_in[7];
    const float* a2d = (const float*)d_in[8];
    const float* b2  = (const float*)d_in[9];
    float* out = (float*)d_out;

    int n = in_sizes[0] / 128;        // 50000
    int E = in_sizes[1] / 2;          // 800000

    __half *p_xh = nullptr, *p_xwh = nullptr, *p_hh = nullptr, *p_bth = nullptr, *p_btl = nullptr;
    cudaGetSymbolAddress((void**)&p_xh,  g_xh);
    cudaGetSymbolAddress((void**)&p_xwh, g_xwh);
    cudaGetSymbolAddress((void**)&p_hh,  g_hh);
    cudaGetSymbolAddress((void**)&p_bth, g_bth);
    cudaGetSymbolAddress((void**)&p_btl, g_btl);

    cudaFuncSetAttribute(gemm_mma_kernel, cudaFuncAttributeMaxDynamicSharedMemorySize, SMEM_DYN);

    int nblk    = (n + 255) / 256;
    int eblk    = (E + 255) / 256;
    int warpBlk = (n * 32 + 255) / 256;
    int sblk    = (n + 1023) / 1024;
    int rtiles  = (n + 127) / 128;    // 391
    dim3 g1(rtiles, 2);               // layer1: N=256
    dim3 g2(rtiles, 1);               // layer2: N=128

    // gemm1 kept in ncu's profiled slot (4th launch)
    initdet_kernel<<<nblk, 256>>>(ei, n);
    x2h_kernel<<<(n * 128 / 8 + 255) / 256, 256>>>(x, n * 128 / 8);
    wt_split_kernel<<<(128 * 256 + 255) / 256, 256>>>(W1, 128, 256);
    gemm_mma_kernel<<<g1, 256, SMEM_DYN>>>(p_xh, 128, p_bth, p_btl, p_xwh, a1s, a1d, n, 256);
    hist_kernel<<<eblk, 256>>>(ei, E);
    blockscan_kernel<<<sblk, 1024>>>(n);
    scanb_kernel<<<1, 32>>>(sblk);
    finish_off_kernel<<<sblk, 1024>>>(n);
    scatter_kernel<<<eblk, 256>>>(ei, E);

    // ---- layer 1 tail ----
    stats_kernel<<<warpBlk, 256>>>(n);
    zero_alpha_kernel<<<nblk, 256>>>(n);
    agg_kernel<256, true, __half><<<warpBlk, 256>>>(p_xwh, b1, p_hh, n);

    // ---- layer 2 ----
    wt_split_kernel<<<(256 * 128 + 255) / 256, 256>>>(W2, 256, 128);
    gemm_mma_kernel<<<g2, 256, SMEM_DYN>>>(p_hh, 256, p_bth, p_btl, p_xwh, a2s, a2d, n, 128);
    stats_kernel<<<warpBlk, 256>>>(n);
    agg_kernel<128, false, float><<<warpBlk, 256>>>(p_xwh, b2, out, n);
}

// round 15
// speedup vs baseline: 1.2411x; 1.0817x over previous
#include <cuda_runtime.h>
#include <cuda_fp16.h>
#include <math.h>
#include <stdint.h>

// ---------------- problem constants ----------------
#define MAXN 50000
#define NPAD 50048              // 391*128 padded rows (scratch only)
#define MAXE 800000
#define MAXTOT (MAXE + MAXN)

// ---------------- device scratch ----------------
__device__ __half g_xh[(size_t)NPAD * 128];  // x converted to fp16
__device__ __half g_xwh[(size_t)NPAD * 256]; // xw of current layer (fp16, gathered)
__device__ __half g_hh[(size_t)NPAD * 256];  // layer-1 output (fp16)
__device__ __half g_bth[32768];              // W1^T hi [N][K] fp16
__device__ __half g_btl[32768];              // W1^T lo
__device__ __half g_bth2[32768];             // W2^T hi
__device__ __half g_btl2[32768];             // W2^T lo
__device__ float g_asrc[MAXN];
__device__ float g_adst[MAXN];
__device__ float g_att[MAXTOT];
__device__ int   g_cnt[MAXN];
__device__ int   g_off[MAXN + 1];
__device__ int   g_csrc[MAXTOT];
__device__ int   g_bsum[64];
__device__ int   g_total;
__device__ int   g_is64;

// ---------------- mma / ldmatrix / cp.async helpers ----------------
__device__ __forceinline__ uint32_t smem_u32(const void* p) {
    uint32_t a;
    asm("{ .reg .u64 t; cvta.to.shared.u64 t, %1; cvt.u32.u64 %0, t; }" : "=r"(a) : "l"(p));
    return a;
}
__device__ __forceinline__ void ldsm4(uint32_t* r, uint32_t addr) {
    asm volatile("ldmatrix.sync.aligned.m8n8.x4.shared.b16 {%0,%1,%2,%3}, [%4];"
        : "=r"(r[0]), "=r"(r[1]), "=r"(r[2]), "=r"(r[3]) : "r"(addr));
}
__device__ __forceinline__ void mma16816h(float* c, const uint32_t* a, const uint32_t* b) {
    asm volatile("mma.sync.aligned.m16n8k16.row.col.f32.f16.f16.f32 "
        "{%0,%1,%2,%3}, {%4,%5,%6,%7}, {%8,%9}, {%0,%1,%2,%3};"
        : "+f"(c[0]), "+f"(c[1]), "+f"(c[2]), "+f"(c[3])
        : "r"(a[0]), "r"(a[1]), "r"(a[2]), "r"(a[3]), "r"(b[0]), "r"(b[1]));
}
__device__ __forceinline__ void cp16(uint32_t dst, const void* src) {
    asm volatile("cp.async.cg.shared.global [%0], [%1], 16;" :: "r"(dst), "l"(src));
}
#define CP_COMMIT() asm volatile("cp.async.commit_group;" ::: "memory")
#define CP_WAIT0()  asm volatile("cp.async.wait_group 0;" ::: "memory")

__device__ __forceinline__ int load_idx(const int* __restrict__ ei, long long elem, int is64) {
    return is64 ? ei[2 * elem] : ei[elem];
}

// ------- prep: dtype sniff + cnt/alpha init + x->fp16 + both W^T splits ------
__global__ void prep_kernel(const int* __restrict__ ei, const float* __restrict__ x,
                            const float* __restrict__ W1, const float* __restrict__ W2,
                            int n, int nx8) {
    int i = blockIdx.x * blockDim.x + threadIdx.x;
    if (i == 0) {
        int z = 1;
        #pragma unroll
        for (int q = 1; q < 64; q += 2)
            if (ei[q] != 0) z = 0;
        g_is64 = z;
    }
    if (i < n) { g_cnt[i] = 1; g_asrc[i] = 0.f; g_adst[i] = 0.f; }
    if (i < nx8) {
        float4 v0 = ((const float4*)x)[2 * i];
        float4 v1 = ((const float4*)x)[2 * i + 1];
        __half hs[8] = {__float2half_rn(v0.x), __float2half_rn(v0.y),
                        __float2half_rn(v0.z), __float2half_rn(v0.w),
                        __float2half_rn(v1.x), __float2half_rn(v1.y),
                        __float2half_rn(v1.z), __float2half_rn(v1.w)};
        ((uint4*)g_xh)[i] = *(uint4*)hs;
    }
    if (i < 32768) {
        {   // W1: K=128, N=256
            int nn = i >> 7, kk = i & 127;
            float v = W1[(size_t)kk * 256 + nn];
            __half h = __float2half_rn(v);
            g_bth[i] = h;
            g_btl[i] = __float2half_rn(v - __half2float(h));
        }
        {   // W2: K=256, N=128
            int nn = i >> 8, kk = i & 255;
            float v = W2[(size_t)kk * 128 + nn];
            __half h = __float2half_rn(v);
            g_bth2[i] = h;
            g_btl2[i] = __float2half_rn(v - __half2float(h));
        }
    }
}

// ---------------- CSR build ----------------
__global__ void hist_kernel(const int* __restrict__ ei, int E) {
    int i = blockIdx.x * blockDim.x + threadIdx.x;
    if (i >= E) return;
    int d = load_idx(ei, (long long)E + i, g_is64);
    atomicAdd(&g_cnt[d], 1);
}
__global__ __launch_bounds__(1024) void blockscan_kernel(int n) {
    __shared__ int warpsum[32];
    int i = blockIdx.x * 1024 + threadIdx.x;
    int v = (i < n) ? g_cnt[i] : 0;
    int lane = threadIdx.x & 31, wid = threadIdx.x >> 5;
    int s = v;
    #pragma unroll
    for (int o = 1; o < 32; o <<= 1) {
        int t = __shfl_up_sync(~0u, s, o);
        if (lane >= o) s += t;
    }
    if (lane == 31) warpsum[wid] = s;
    __syncthreads();
    if (wid == 0) {
        int ws = warpsum[lane];
        #pragma unroll
        for (int o = 1; o < 32; o <<= 1) {
            int t = __shfl_up_sync(~0u, ws, o);
            if (lane >= o) ws += t;
        }
        warpsum[lane] = ws;
    }
    __syncthreads();
    int excl = s - v + (wid ? warpsum[wid - 1] : 0);
    if (i < n) g_off[i] = excl;
    if (threadIdx.x == 1023) g_bsum[blockIdx.x] = excl + v;
}
__global__ void scanb_kernel(int nb) {
    if (threadIdx.x == 0 && blockIdx.x == 0) {
        int run = 0;
        for (int b = 0; b < nb; b++) { int t = g_bsum[b]; g_bsum[b] = run; run += t; }
        g_total = run;
    }
}
__global__ void finish_off_kernel(int n) {
    int i = blockIdx.x * 1024 + threadIdx.x;
    if (i < n) {
        int off = g_off[i] + g_bsum[i >> 10];
        g_off[i] = off;
        g_csrc[off] = i;
        g_cnt[i] = off + 1;
    }
    if (i == 0) g_off[n] = g_total;
}
__global__ void scatter_kernel(const int* __restrict__ ei, int E) {
    int i = blockIdx.x * blockDim.x + threadIdx.x;
    if (i >= E) return;
    int is64 = g_is64;
    int s = load_idx(ei, i, is64);
    int d = load_idx(ei, (long long)E + i, is64);
    int p = atomicAdd(&g_cnt[d], 1);
    g_csrc[p] = s;
}

// ---- GEMM: block 128x128, 8 warps (2Mx4N), warp 64x32, fp16 mma, cp.async ---
#define LDP 80
#define OFF_BH 10240
#define OFF_BL 20480
#define STAGE_B 30720
#define SMEM_DYN (2 * STAGE_B)

__global__ __launch_bounds__(256, 2) void gemm_mma_kernel(
    const __half* __restrict__ A, int Kfull,
    const __half* __restrict__ Bth, const __half* __restrict__ Btl,
    __half* __restrict__ C,
    const float* __restrict__ avs, const float* __restrict__ avd,
    int M, int N)
{
    extern __shared__ __align__(16) char buf[];
    uint32_t sb = smem_u32(buf);

    int tid = threadIdx.x;
    int w = tid >> 5, lane = tid & 31;
    int wr = w >> 2, wc = w & 3;                 // warp tile 64(M) x 32(N)
    int r0 = blockIdx.x * 128, c0 = blockIdx.y * 128;

    float acc[4][4][4];
    #pragma unroll
    for (int mt = 0; mt < 4; mt++)
        #pragma unroll
        for (int nt = 0; nt < 4; nt++)
            #pragma unroll
            for (int q = 0; q < 4; q++) acc[mt][nt][q] = 0.f;

    int la_row = (lane & 15), la_k = (lane >> 4) * 8;
    uint32_t a_frag_off = (uint32_t)(la_row * LDP + la_k * 2);
    int lb_n = (lane & 7) + ((lane >> 4) & 1) * 8;
    int lb_k = ((lane >> 3) & 1) * 8;
    uint32_t b_frag_off = (uint32_t)(lb_n * LDP + lb_k * 2);

    int steps = Kfull / 32;

    auto stage_load = [&](uint32_t st, int k0) {
        #pragma unroll
        for (int j = 0; j < 2; j++) {
            int c = tid + 256 * j;
            int row = c >> 2, col = (c & 3) * 8;
            uint32_t doff = (uint32_t)(row * LDP + col * 2);
            cp16(st + doff,          A   + (size_t)(r0 + row) * Kfull + k0 + col);
            size_t bo = (size_t)(c0 + row) * Kfull + k0 + col;
            cp16(st + OFF_BH + doff, Bth + bo);
            cp16(st + OFF_BL + doff, Btl + bo);
        }
        CP_COMMIT();
    };

    stage_load(sb, 0);
    CP_WAIT0();
    __syncthreads();

    for (int i = 0; i < steps; i++) {
        uint32_t st = sb + (uint32_t)(i & 1) * STAGE_B;
        if (i + 1 < steps) stage_load(sb + (uint32_t)((i + 1) & 1) * STAGE_B, (i + 1) * 32);
        #pragma unroll
        for (int ks = 0; ks < 2; ks++) {
            uint32_t koff = (uint32_t)(ks * 32);
            uint32_t bh[2][4], bl[2][4];
            #pragma unroll
            for (int np = 0; np < 2; np++) {
                uint32_t nbase = st + OFF_BH + (uint32_t)((wc * 32 + np * 16) * LDP) + b_frag_off + koff;
                ldsm4(bh[np], nbase);
                ldsm4(bl[np], nbase + (OFF_BL - OFF_BH));
            }
            #pragma unroll
            for (int mt = 0; mt < 4; mt++) {
                uint32_t af[4];
                ldsm4(af, st + (uint32_t)((wr * 64 + mt * 16) * LDP) + a_frag_off + koff);
                #pragma unroll
                for (int nt = 0; nt < 4; nt++) {
                    const uint32_t* bhp = &bh[nt >> 1][(nt & 1) * 2];
                    const uint32_t* blp = &bl[nt >> 1][(nt & 1) * 2];
                    mma16816h(acc[mt][nt], af, bhp);
                    mma16816h(acc[mt][nt], af, blp);
                }
            }
        }
        CP_WAIT0();
        __syncthreads();
    }

    // ---- store C (fp16) + fused alpha partials from fp32 accumulators ----
    {
        float as[4][2], ad[4][2];
        #pragma unroll
        for (int nt = 0; nt < 4; nt++) {
            int col = c0 + wc * 32 + nt * 8 + (lane & 3) * 2;
            as[nt][0] = avs[col];     as[nt][1] = avs[col + 1];
            ad[nt][0] = avd[col];     ad[nt][1] = avd[col + 1];
        }
        #pragma unroll
        for (int mt = 0; mt < 4; mt++) {
            int rA = r0 + wr * 64 + mt * 16 + (lane >> 2);
            int rB = rA + 8;
            float ssA = 0.f, sdA = 0.f, ssB = 0.f, sdB = 0.f;
            #pragma unroll
            for (int nt = 0; nt < 4; nt++) {
                float* c = acc[mt][nt];
                int col = c0 + wc * 32 + nt * 8 + (lane & 3) * 2;
                *(__half2*)(C + (size_t)rA * N + col) = __floats2half2_rn(c[0], c[1]);
                *(__half2*)(C + (size_t)rB * N + col) = __floats2half2_rn(c[2], c[3]);
                ssA += c[0] * as[nt][0] + c[1] * as[nt][1];
                sdA += c[0] * ad[nt][0] + c[1] * ad[nt][1];
                ssB += c[2] * as[nt][0] + c[3] * as[nt][1];
                sdB += c[2] * ad[nt][0] + c[3] * ad[nt][1];
            }
            #pragma unroll
            for (int o = 1; o < 4; o <<= 1) {
                ssA += __shfl_xor_sync(~0u, ssA, o);
                sdA += __shfl_xor_sync(~0u, sdA, o);
                ssB += __shfl_xor_sync(~0u, ssB, o);
                sdB += __shfl_xor_sync(~0u, sdB, o);
            }
            if ((lane & 3) == 0) {
                if (rA < M) { atomicAdd(&g_asrc[rA], ssA); atomicAdd(&g_adst[rA], sdA); }
                if (rB < M) { atomicAdd(&g_asrc[rB], ssB); atomicAdd(&g_adst[rB], sdB); }
            }
        }
    }
}

// ---------------- segment softmax: stats + normalized att per edge ----------
__global__ void stats_kernel(int n) {
    int w = (blockIdx.x * blockDim.x + threadIdx.x) >> 5;
    int lane = threadIdx.x & 31;
    if (w >= n) return;
    int beg = g_off[w], end = g_off[w + 1];
    float adi = g_adst[w];
    float mx = -1e30f, sm = 0.f;
    for (int k = beg + lane; k < end; k += 32) {
        int s = g_csrc[k];
        float e = g_asrc[s] + adi;
        e = e >= 0.f ? e : 0.2f * e;
        if (e > mx) { sm = sm * __expf(mx - e) + 1.f; mx = e; }
        else        { sm += __expf(e - mx); }
    }
    #pragma unroll
    for (int o = 16; o; o >>= 1) {
        float mo = __shfl_xor_sync(~0u, mx, o);
        float so = __shfl_xor_sync(~0u, sm, o);
        float nm = fmaxf(mx, mo);
        sm = sm * __expf(mx - nm) + so * __expf(mo - nm);
        mx = nm;
    }
    float inv = 1.f / sm;
    for (int k = beg + lane; k < end; k += 32) {
        int s = g_csrc[k];
        float e = g_asrc[s] + adi;
        e = e >= 0.f ? e : 0.2f * e;
        g_att[k] = __expf(e - mx) * inv;
    }
}

// -- aggregation (warp per node, fp16 gather, fp32 acc; optional alpha-zero) --
template<int F, bool RELU, typename OutT, bool ZEROA>
__global__ void agg_kernel(const __half* __restrict__ xw,
                           const float* __restrict__ bias,
                           OutT* __restrict__ out, int n)
{
    int w = (blockIdx.x * blockDim.x + threadIdx.x) >> 5;
    int lane = threadIdx.x & 31;
    if (w >= n) return;
    const int NV = F / 32;
    int beg = g_off[w], end = g_off[w + 1];
    float acc[NV];
    #pragma unroll
    for (int q = 0; q < NV; q++) acc[q] = 0.f;

    int k = beg;
    for (; k + 2 <= end; k += 2) {
        int s0 = g_csrc[k], s1 = g_csrc[k + 1];
        float a0 = g_att[k], a1 = g_att[k + 1];
        const __half* r0p = xw + (size_t)s0 * F + lane * NV;
        const __half* r1p = xw + (size_t)s1 * F + lane * NV;
        if (NV == 8) {
            uint4 u0 = *(const uint4*)r0p;
            uint4 u1 = *(const uint4*)r1p;
            const __half2* h0 = (const __half2*)&u0;
            const __half2* h1 = (const __half2*)&u1;
            #pragma unroll
            for (int q = 0; q < 4; q++) {
                float2 f0 = __half22float2(h0[q]);
                float2 f1 = __half22float2(h1[q]);
                acc[2*q]   += a0 * f0.x + a1 * f1.x;
                acc[2*q+1] += a0 * f0.y + a1 * f1.y;
            }
        } else {
            uint2 u0 = *(const uint2*)r0p;
            uint2 u1 = *(const uint2*)r1p;
            const __half2* h0 = (const __half2*)&u0;
            const __half2* h1 = (const __half2*)&u1;
            #pragma unroll
            for (int q = 0; q < 2; q++) {
                float2 f0 = __half22float2(h0[q]);
                float2 f1 = __half22float2(h1[q]);
                acc[2*q]   += a0 * f0.x + a1 * f1.x;
                acc[2*q+1] += a0 * f0.y + a1 * f1.y;
            }
        }
    }
    if (k < end) {
        int s0 = g_csrc[k];
        float a0 = g_att[k];
        const __half* r0p = xw + (size_t)s0 * F + lane * NV;
        if (NV == 8) {
            uint4 u0 = *(const uint4*)r0p;
            const __half2* h0 = (const __half2*)&u0;
            #pragma unroll
            for (int q = 0; q < 4; q++) {
                float2 f0 = __half22float2(h0[q]);
                acc[2*q]   += a0 * f0.x;
                acc[2*q+1] += a0 * f0.y;
            }
        } else {
            uint2 u0 = *(const uint2*)r0p;
            const __half2* h0 = (const __half2*)&u0;
            #pragma unroll
            for (int q = 0; q < 2; q++) {
                float2 f0 = __half22float2(h0[q]);
                acc[2*q]   += a0 * f0.x;
                acc[2*q+1] += a0 * f0.y;
            }
        }
    }
    if (ZEROA && lane == 0) { g_asrc[w] = 0.f; g_adst[w] = 0.f; }
    const float* bp = bias + lane * NV;
    #pragma unroll
    for (int q = 0; q < NV; q++) {
        float v = acc[q] + bp[q];
        if (RELU) v = fmaxf(v, 0.f);
        acc[q] = v;
    }
    if (sizeof(OutT) == 2) {
        __half* op = (__half*)out + (size_t)w * F + lane * NV;
        #pragma unroll
        for (int q = 0; q < NV; q += 2)
            *(__half2*)(op + q) = __floats2half2_rn(acc[q], acc[q+1]);
    } else {
        float* op = (float*)out + (size_t)w * F + lane * NV;
        #pragma unroll
        for (int q = 0; q < NV; q += 4)
            *(float4*)(op + q) = make_float4(acc[q], acc[q+1], acc[q+2], acc[q+3]);
    }
}

// ---------------- launch ----------------
extern "C" void kernel_launch(void* const* d_in, const int* in_sizes, int n_in,
                              void* d_out, int out_size) {
    const float* x   = (const float*)d_in[0];
    const int*   ei  = (const int*)d_in[1];
    const float* W1  = (const float*)d_in[2];
    const float* a1s = (const float*)d_in[3];
    const float* a1d = (const float*)d_in[4];
    const float* b1  = (const float*)d_in[5];
    const float* W2  = (const float*)d_in[6];
    const float* a2s = (const float*)d_in[7];
    const float* a2d = (const float*)d_in[8];
    const float* b2  = (const float*)d_in[9];
    float* out = (float*)d_out;

    int n = in_sizes[0] / 128;        // 50000
    int E = in_sizes[1] / 2;          // 800000
    int nx8 = n * 16;                 // x fp16-convert chunks

    __half *p_xh, *p_xwh, *p_hh, *p_bth, *p_btl, *p_bth2, *p_btl2;
    cudaGetSymbolAddress((void**)&p_xh,   g_xh);
    cudaGetSymbolAddress((void**)&p_xwh,  g_xwh);
    cudaGetSymbolAddress((void**)&p_hh,   g_hh);
    cudaGetSymbolAddress((void**)&p_bth,  g_bth);
    cudaGetSymbolAddress((void**)&p_btl,  g_btl);
    cudaGetSymbolAddress((void**)&p_bth2, g_bth2);
    cudaGetSymbolAddress((void**)&p_btl2, g_btl2);

    cudaFuncSetAttribute(gemm_mma_kernel, cudaFuncAttributeMaxDynamicSharedMemorySize, SMEM_DYN);

    int eblk    = (E + 255) / 256;
    int warpBlk = (n * 32 + 255) / 256;
    int sblk    = (n + 1023) / 1024;
    int rtiles  = (n + 127) / 128;    // 391
    dim3 g1(rtiles, 2);               // layer1: N=256
    dim3 g2(rtiles, 1);               // layer2: N=128

    // side stream + fork/join events (host-side objects; created per call, leaked)
    cudaStream_t s2;
    cudaStreamCreateWithFlags(&s2, cudaStreamNonBlocking);
    cudaEvent_t evF, evJ;
    cudaEventCreateWithFlags(&evF, cudaEventDisableTiming);
    cudaEventCreateWithFlags(&evJ, cudaEventDisableTiming);

    // prep: everything both branches need
    prep_kernel<<<(nx8 + 255) / 256, 256>>>(ei, x, W1, W2, n, nx8);
    cudaEventRecord(evF, 0);
    cudaStreamWaitEvent(s2, evF, 0);

    // side stream: CSR build (independent of GEMM1)
    hist_kernel<<<eblk, 256, 0, s2>>>(ei, E);
    blockscan_kernel<<<sblk, 1024, 0, s2>>>(n);
    scanb_kernel<<<1, 32, 0, s2>>>(sblk);
    finish_off_kernel<<<sblk, 1024, 0, s2>>>(n);
    scatter_kernel<<<eblk, 256, 0, s2>>>(ei, E);
    cudaEventRecord(evJ, s2);

    // main stream: GEMM1 overlaps the CSR chain
    gemm_mma_kernel<<<g1, 256, SMEM_DYN>>>(p_xh, 128, p_bth, p_btl, p_xwh, a1s, a1d, n, 256);
    cudaStreamWaitEvent(0, evJ, 0);

    // layer 1 tail (needs CSR + GEMM1)
    stats_kernel<<<warpBlk, 256>>>(n);
    agg_kernel<256, true, __half, true><<<warpBlk, 256>>>(p_xwh, b1, p_hh, n);

    // layer 2
    gemm_mma_kernel<<<g2, 256, SMEM_DYN>>>(p_hh, 256, p_bth2, p_btl2, p_xwh, a2s, a2d, n, 128);
    stats_kernel<<<warpBlk, 256>>>(n);
    agg_kernel<128, false, float, false><<<warpBlk, 256>>>(p_xwh, b2, out, n);
}

// round 16
// speedup vs baseline: 1.2676x; 1.0213x over previous
#include <cuda_runtime.h>
#include <cuda_fp16.h>
#include <math.h>
#include <stdint.h>

// ---------------- problem constants ----------------
#define MAXN 50000
#define NPAD 50048              // 391*128 padded rows (scratch only)
#define MAXE 800000
#define MAXTOT (MAXE + MAXN)

// ---------------- device scratch ----------------
__device__ __half g_xh[(size_t)NPAD * 128];  // x converted to fp16
__device__ __half g_xwh[(size_t)NPAD * 256]; // xw of current layer (fp16, gathered)
__device__ __half g_hh[(size_t)NPAD * 256];  // layer-1 output (fp16)
__device__ __half g_bth[32768];              // W1^T hi [N][K] fp16
__device__ __half g_btl[32768];              // W1^T lo
__device__ __half g_bth2[32768];             // W2^T hi
__device__ __half g_btl2[32768];             // W2^T lo
__device__ float g_asrc[MAXN];
__device__ float g_adst[MAXN];
__device__ float g_att[MAXTOT];              // raw e, then normalized att (in place)
__device__ int   g_cnt[MAXN];
__device__ int   g_off[MAXN + 1];
__device__ int   g_csrc[MAXTOT];
__device__ int   g_bsum[64];
__device__ int   g_total;
__device__ int   g_is64;

// ---------------- mma / ldmatrix / cp.async helpers ----------------
__device__ __forceinline__ uint32_t smem_u32(const void* p) {
    uint32_t a;
    asm("{ .reg .u64 t; cvta.to.shared.u64 t, %1; cvt.u32.u64 %0, t; }" : "=r"(a) : "l"(p));
    return a;
}
__device__ __forceinline__ void ldsm4(uint32_t* r, uint32_t addr) {
    asm volatile("ldmatrix.sync.aligned.m8n8.x4.shared.b16 {%0,%1,%2,%3}, [%4];"
        : "=r"(r[0]), "=r"(r[1]), "=r"(r[2]), "=r"(r[3]) : "r"(addr));
}
__device__ __forceinline__ void mma16816h(float* c, const uint32_t* a, const uint32_t* b) {
    asm volatile("mma.sync.aligned.m16n8k16.row.col.f32.f16.f16.f32 "
        "{%0,%1,%2,%3}, {%4,%5,%6,%7}, {%8,%9}, {%0,%1,%2,%3};"
        : "+f"(c[0]), "+f"(c[1]), "+f"(c[2]), "+f"(c[3])
        : "r"(a[0]), "r"(a[1]), "r"(a[2]), "r"(a[3]), "r"(b[0]), "r"(b[1]));
}
__device__ __forceinline__ void cp16(uint32_t dst, const void* src) {
    asm volatile("cp.async.cg.shared.global [%0], [%1], 16;" :: "r"(dst), "l"(src));
}
#define CP_COMMIT() asm volatile("cp.async.commit_group;" ::: "memory")
#define CP_WAIT0()  asm volatile("cp.async.wait_group 0;" ::: "memory")

__device__ __forceinline__ int load_idx(const int* __restrict__ ei, long long elem, int is64) {
    return is64 ? ei[2 * elem] : ei[elem];
}

// ------- prep: dtype sniff + cnt/alpha init + x->fp16 + both W^T splits ------
__global__ void prep_kernel(const int* __restrict__ ei, const float* __restrict__ x,
                            const float* __restrict__ W1, const float* __restrict__ W2,
                            int n, int nx8) {
    int i = blockIdx.x * blockDim.x + threadIdx.x;
    if (i == 0) {
        int z = 1;
        #pragma unroll
        for (int q = 1; q < 64; q += 2)
            if (ei[q] != 0) z = 0;
        g_is64 = z;
    }
    if (i < n) { g_cnt[i] = 1; g_asrc[i] = 0.f; g_adst[i] = 0.f; }
    if (i < nx8) {
        float4 v0 = ((const float4*)x)[2 * i];
        float4 v1 = ((const float4*)x)[2 * i + 1];
        __half hs[8] = {__float2half_rn(v0.x), __float2half_rn(v0.y),
                        __float2half_rn(v0.z), __float2half_rn(v0.w),
                        __float2half_rn(v1.x), __float2half_rn(v1.y),
                        __float2half_rn(v1.z), __float2half_rn(v1.w)};
        ((uint4*)g_xh)[i] = *(uint4*)hs;
    }
    if (i < 32768) {
        {   // W1: K=128, N=256
            int nn = i >> 7, kk = i & 127;
            float v = W1[(size_t)kk * 256 + nn];
            __half h = __float2half_rn(v);
            g_bth[i] = h;
            g_btl[i] = __float2half_rn(v - __half2float(h));
        }
        {   // W2: K=256, N=128
            int nn = i >> 8, kk = i & 255;
            float v = W2[(size_t)kk * 128 + nn];
            __half h = __float2half_rn(v);
            g_bth2[i] = h;
            g_btl2[i] = __float2half_rn(v - __half2float(h));
        }
    }
}

// ---------------- CSR build ----------------
__global__ void hist_kernel(const int* __restrict__ ei, int E) {
    int i = blockIdx.x * blockDim.x + threadIdx.x;
    if (i >= E) return;
    int d = load_idx(ei, (long long)E + i, g_is64);
    atomicAdd(&g_cnt[d], 1);
}
__global__ __launch_bounds__(1024) void blockscan_kernel(int n) {
    __shared__ int warpsum[32];
    int i = blockIdx.x * 1024 + threadIdx.x;
    int v = (i < n) ? g_cnt[i] : 0;
    int lane = threadIdx.x & 31, wid = threadIdx.x >> 5;
    int s = v;
    #pragma unroll
    for (int o = 1; o < 32; o <<= 1) {
        int t = __shfl_up_sync(~0u, s, o);
        if (lane >= o) s += t;
    }
    if (lane == 31) warpsum[wid] = s;
    __syncthreads();
    if (wid == 0) {
        int ws = warpsum[lane];
        #pragma unroll
        for (int o = 1; o < 32; o <<= 1) {
            int t = __shfl_up_sync(~0u, ws, o);
            if (lane >= o) ws += t;
        }
        warpsum[lane] = ws;
    }
    __syncthreads();
    int excl = s - v + (wid ? warpsum[wid - 1] : 0);
    if (i < n) g_off[i] = excl;
    if (threadIdx.x == 1023) g_bsum[blockIdx.x] = excl + v;
}
__global__ void scanb_kernel(int nb) {
    if (threadIdx.x == 0 && blockIdx.x == 0) {
        int run = 0;
        for (int b = 0; b < nb; b++) { int t = g_bsum[b]; g_bsum[b] = run; run += t; }
        g_total = run;
    }
}
__global__ void finish_off_kernel(int n) {
    int i = blockIdx.x * 1024 + threadIdx.x;
    if (i < n) {
        int off = g_off[i] + g_bsum[i >> 10];
        g_off[i] = off;
        g_csrc[off] = i;
        g_cnt[i] = off + 1;
    }
    if (i == 0) g_off[n] = g_total;
}
__global__ void scatter_kernel(const int* __restrict__ ei, int E) {
    int i = blockIdx.x * blockDim.x + threadIdx.x;
    if (i >= E) return;
    int is64 = g_is64;
    int s = load_idx(ei, i, is64);
    int d = load_idx(ei, (long long)E + i, is64);
    int p = atomicAdd(&g_cnt[d], 1);
    g_csrc[p] = s;
}

// ---- GEMM: block 128x128, 8 warps (2Mx4N), warp 64x32, fp16 mma, cp.async ---
#define LDP 80
#define OFF_BH 10240
#define OFF_BL 20480
#define STAGE_B 30720
#define SMEM_DYN (2 * STAGE_B)

__global__ __launch_bounds__(256, 2) void gemm_mma_kernel(
    const __half* __restrict__ A, int Kfull,
    const __half* __restrict__ Bth, const __half* __restrict__ Btl,
    __half* __restrict__ C,
    const float* __restrict__ avs, const float* __restrict__ avd,
    int M, int N)
{
    extern __shared__ __align__(16) char buf[];
    uint32_t sb = smem_u32(buf);

    int tid = threadIdx.x;
    int w = tid >> 5, lane = tid & 31;
    int wr = w >> 2, wc = w & 3;                 // warp tile 64(M) x 32(N)
    int r0 = blockIdx.x * 128, c0 = blockIdx.y * 128;

    float acc[4][4][4];
    #pragma unroll
    for (int mt = 0; mt < 4; mt++)
        #pragma unroll
        for (int nt = 0; nt < 4; nt++)
            #pragma unroll
            for (int q = 0; q < 4; q++) acc[mt][nt][q] = 0.f;

    int la_row = (lane & 15), la_k = (lane >> 4) * 8;
    uint32_t a_frag_off = (uint32_t)(la_row * LDP + la_k * 2);
    int lb_n = (lane & 7) + ((lane >> 4) & 1) * 8;
    int lb_k = ((lane >> 3) & 1) * 8;
    uint32_t b_frag_off = (uint32_t)(lb_n * LDP + lb_k * 2);

    int steps = Kfull / 32;

    auto stage_load = [&](uint32_t st, int k0) {
        #pragma unroll
        for (int j = 0; j < 2; j++) {
            int c = tid + 256 * j;
            int row = c >> 2, col = (c & 3) * 8;
            uint32_t doff = (uint32_t)(row * LDP + col * 2);
            cp16(st + doff,          A   + (size_t)(r0 + row) * Kfull + k0 + col);
            size_t bo = (size_t)(c0 + row) * Kfull + k0 + col;
            cp16(st + OFF_BH + doff, Bth + bo);
            cp16(st + OFF_BL + doff, Btl + bo);
        }
        CP_COMMIT();
    };

    stage_load(sb, 0);
    CP_WAIT0();
    __syncthreads();

    for (int i = 0; i < steps; i++) {
        uint32_t st = sb + (uint32_t)(i & 1) * STAGE_B;
        if (i + 1 < steps) stage_load(sb + (uint32_t)((i + 1) & 1) * STAGE_B, (i + 1) * 32);
        #pragma unroll
        for (int ks = 0; ks < 2; ks++) {
            uint32_t koff = (uint32_t)(ks * 32);
            uint32_t bh[2][4], bl[2][4];
            #pragma unroll
            for (int np = 0; np < 2; np++) {
                uint32_t nbase = st + OFF_BH + (uint32_t)((wc * 32 + np * 16) * LDP) + b_frag_off + koff;
                ldsm4(bh[np], nbase);
                ldsm4(bl[np], nbase + (OFF_BL - OFF_BH));
            }
            #pragma unroll
            for (int mt = 0; mt < 4; mt++) {
                uint32_t af[4];
                ldsm4(af, st + (uint32_t)((wr * 64 + mt * 16) * LDP) + a_frag_off + koff);
                #pragma unroll
                for (int nt = 0; nt < 4; nt++) {
                    const uint32_t* bhp = &bh[nt >> 1][(nt & 1) * 2];
                    const uint32_t* blp = &bl[nt >> 1][(nt & 1) * 2];
                    mma16816h(acc[mt][nt], af, bhp);
                    mma16816h(acc[mt][nt], af, blp);
                }
            }
        }
        CP_WAIT0();
        __syncthreads();
    }

    // ---- store C (fp16) + fused alpha partials from fp32 accumulators ----
    {
        float as[4][2], ad[4][2];
        #pragma unroll
        for (int nt = 0; nt < 4; nt++) {
            int col = c0 + wc * 32 + nt * 8 + (lane & 3) * 2;
            as[nt][0] = avs[col];     as[nt][1] = avs[col + 1];
            ad[nt][0] = avd[col];     ad[nt][1] = avd[col + 1];
        }
        #pragma unroll
        for (int mt = 0; mt < 4; mt++) {
            int rA = r0 + wr * 64 + mt * 16 + (lane >> 2);
            int rB = rA + 8;
            float ssA = 0.f, sdA = 0.f, ssB = 0.f, sdB = 0.f;
            #pragma unroll
            for (int nt = 0; nt < 4; nt++) {
                float* c = acc[mt][nt];
                int col = c0 + wc * 32 + nt * 8 + (lane & 3) * 2;
                *(__half2*)(C + (size_t)rA * N + col) = __floats2half2_rn(c[0], c[1]);
                *(__half2*)(C + (size_t)rB * N + col) = __floats2half2_rn(c[2], c[3]);
                ssA += c[0] * as[nt][0] + c[1] * as[nt][1];
                sdA += c[0] * ad[nt][0] + c[1] * ad[nt][1];
                ssB += c[2] * as[nt][0] + c[3] * as[nt][1];
                sdB += c[2] * ad[nt][0] + c[3] * ad[nt][1];
            }
            #pragma unroll
            for (int o = 1; o < 4; o <<= 1) {
                ssA += __shfl_xor_sync(~0u, ssA, o);
                sdA += __shfl_xor_sync(~0u, sdA, o);
                ssB += __shfl_xor_sync(~0u, ssB, o);
                sdB += __shfl_xor_sync(~0u, sdB, o);
            }
            if ((lane & 3) == 0) {
                if (rA < M) { atomicAdd(&g_asrc[rA], ssA); atomicAdd(&g_adst[rA], sdA); }
                if (rB < M) { atomicAdd(&g_asrc[rB], ssB); atomicAdd(&g_adst[rB], sdB); }
            }
        }
    }
}

// ------- segment softmax: pass1 gather+store raw e; pass2 sequential norm ----
__global__ void stats_kernel(int n) {
    int w = (blockIdx.x * blockDim.x + threadIdx.x) >> 5;
    int lane = threadIdx.x & 31;
    if (w >= n) return;
    int beg = g_off[w], end = g_off[w + 1];
    float adi = g_adst[w];
    float mx = -1e30f, sm = 0.f;
    for (int k = beg + lane; k < end; k += 32) {
        int s = g_csrc[k];
        float e = g_asrc[s] + adi;
        e = e >= 0.f ? e : 0.2f * e;
        g_att[k] = e;                               // raw e, coalesced-ish write
        if (e > mx) { sm = sm * __expf(mx - e) + 1.f; mx = e; }
        else        { sm += __expf(e - mx); }
    }
    #pragma unroll
    for (int o = 16; o; o >>= 1) {
        float mo = __shfl_xor_sync(~0u, mx, o);
        float so = __shfl_xor_sync(~0u, sm, o);
        float nm = fmaxf(mx, mo);
        sm = sm * __expf(mx - nm) + so * __expf(mo - nm);
        mx = nm;
    }
    float inv = 1.f / sm;
    for (int k = beg + lane; k < end; k += 32) {    // sequential in-place normalize
        float e = g_att[k];
        g_att[k] = __expf(e - mx) * inv;
    }
}

// -- aggregation (warp/node, fp16 gather, 4-edge unroll; optional alpha-zero) -
template<int F, bool RELU, typename OutT, bool ZEROA>
__global__ void agg_kernel(const __half* __restrict__ xw,
                           const float* __restrict__ bias,
                           OutT* __restrict__ out, int n)
{
    int w = (blockIdx.x * blockDim.x + threadIdx.x) >> 5;
    int lane = threadIdx.x & 31;
    if (w >= n) return;
    const int NV = F / 32;
    int beg = g_off[w], end = g_off[w + 1];
    float acc[NV];
    #pragma unroll
    for (int q = 0; q < NV; q++) acc[q] = 0.f;

    int k = beg;
    for (; k + 4 <= end; k += 4) {
        int   s[4];
        float a[4];
        #pragma unroll
        for (int j = 0; j < 4; j++) { s[j] = g_csrc[k + j]; a[j] = g_att[k + j]; }
        if (NV == 8) {
            uint4 u[4];
            #pragma unroll
            for (int j = 0; j < 4; j++)
                u[j] = *(const uint4*)(xw + (size_t)s[j] * F + lane * NV);
            #pragma unroll
            for (int j = 0; j < 4; j++) {
                const __half2* h = (const __half2*)&u[j];
                #pragma unroll
                for (int q = 0; q < 4; q++) {
                    float2 f = __half22float2(h[q]);
                    acc[2*q]   += a[j] * f.x;
                    acc[2*q+1] += a[j] * f.y;
                }
            }
        } else {
            uint2 u[4];
            #pragma unroll
            for (int j = 0; j < 4; j++)
                u[j] = *(const uint2*)(xw + (size_t)s[j] * F + lane * NV);
            #pragma unroll
            for (int j = 0; j < 4; j++) {
                const __half2* h = (const __half2*)&u[j];
                #pragma unroll
                for (int q = 0; q < 2; q++) {
                    float2 f = __half22float2(h[q]);
                    acc[2*q]   += a[j] * f.x;
                    acc[2*q+1] += a[j] * f.y;
                }
            }
        }
    }
    for (; k < end; k++) {
        int s0 = g_csrc[k];
        float a0 = g_att[k];
        const __half* rp = xw + (size_t)s0 * F + lane * NV;
        if (NV == 8) {
            uint4 u0 = *(const uint4*)rp;
            const __half2* h0 = (const __half2*)&u0;
            #pragma unroll
            for (int q = 0; q < 4; q++) {
                float2 f0 = __half22float2(h0[q]);
                acc[2*q]   += a0 * f0.x;
                acc[2*q+1] += a0 * f0.y;
            }
        } else {
            uint2 u0 = *(const uint2*)rp;
            const __half2* h0 = (const __half2*)&u0;
            #pragma unroll
            for (int q = 0; q < 2; q++) {
                float2 f0 = __half22float2(h0[q]);
                acc[2*q]   += a0 * f0.x;
                acc[2*q+1] += a0 * f0.y;
            }
        }
    }
    if (ZEROA && lane == 0) { g_asrc[w] = 0.f; g_adst[w] = 0.f; }
    const float* bp = bias + lane * NV;
    #pragma unroll
    for (int q = 0; q < NV; q++) {
        float v = acc[q] + bp[q];
        if (RELU) v = fmaxf(v, 0.f);
        acc[q] = v;
    }
    if (sizeof(OutT) == 2) {
        __half* op = (__half*)out + (size_t)w * F + lane * NV;
        #pragma unroll
        for (int q = 0; q < NV; q += 2)
            *(__half2*)(op + q) = __floats2half2_rn(acc[q], acc[q+1]);
    } else {
        float* op = (float*)out + (size_t)w * F + lane * NV;
        #pragma unroll
        for (int q = 0; q < NV; q += 4)
            *(float4*)(op + q) = make_float4(acc[q], acc[q+1], acc[q+2], acc[q+3]);
    }
}

// ---------------- launch ----------------
extern "C" void kernel_launch(void* const* d_in, const int* in_sizes, int n_in,
                              void* d_out, int out_size) {
    const float* x   = (const float*)d_in[0];
    const int*   ei  = (const int*)d_in[1];
    const float* W1  = (const float*)d_in[2];
    const float* a1s = (const float*)d_in[3];
    const float* a1d = (const float*)d_in[4];
    const float* b1  = (const float*)d_in[5];
    const float* W2  = (const float*)d_in[6];
    const float* a2s = (const float*)d_in[7];
    const float* a2d = (const float*)d_in[8];
    const float* b2  = (const float*)d_in[9];
    float* out = (float*)d_out;

    int n = in_sizes[0] / 128;        // 50000
    int E = in_sizes[1] / 2;          // 800000
    int nx8 = n * 16;

    __half *p_xh, *p_xwh, *p_hh, *p_bth, *p_btl, *p_bth2, *p_btl2;
    cudaGetSymbolAddress((void**)&p_xh,   g_xh);
    cudaGetSymbolAddress((void**)&p_xwh,  g_xwh);
    cudaGetSymbolAddress((void**)&p_hh,   g_hh);
    cudaGetSymbolAddress((void**)&p_bth,  g_bth);
    cudaGetSymbolAddress((void**)&p_btl,  g_btl);
    cudaGetSymbolAddress((void**)&p_bth2, g_bth2);
    cudaGetSymbolAddress((void**)&p_btl2, g_btl2);

    cudaFuncSetAttribute(gemm_mma_kernel, cudaFuncAttributeMaxDynamicSharedMemorySize, SMEM_DYN);

    int eblk    = (E + 255) / 256;
    int warpBlk = (n * 32 + 255) / 256;
    int sblk    = (n + 1023) / 1024;
    int rtiles  = (n + 127) / 128;    // 391
    dim3 g1(rtiles, 2);
    dim3 g2(rtiles, 1);

    // side stream + fork/join events (host-side objects; created per call, leaked)
    cudaStream_t s2;
    cudaStreamCreateWithFlags(&s2, cudaStreamNonBlocking);
    cudaEvent_t evF, evJ;
    cudaEventCreateWithFlags(&evF, cudaEventDisableTiming);
    cudaEventCreateWithFlags(&evJ, cudaEventDisableTiming);

    prep_kernel<<<(nx8 + 255) / 256, 256>>>(ei, x, W1, W2, n, nx8);
    cudaEventRecord(evF, 0);
    cudaStreamWaitEvent(s2, evF, 0);

    // side stream: CSR build (overlaps GEMM1)
    hist_kernel<<<eblk, 256, 0, s2>>>(ei, E);
    blockscan_kernel<<<sblk, 1024, 0, s2>>>(n);
    scanb_kernel<<<1, 32, 0, s2>>>(sblk);
    finish_off_kernel<<<sblk, 1024, 0, s2>>>(n);
    scatter_kernel<<<eblk, 256, 0, s2>>>(ei, E);
    cudaEventRecord(evJ, s2);

    // main stream
    gemm_mma_kernel<<<g1, 256, SMEM_DYN>>>(p_xh, 128, p_bth, p_btl, p_xwh, a1s, a1d, n, 256);
    cudaStreamWaitEvent(0, evJ, 0);

    stats_kernel<<<warpBlk, 256>>>(n);
    agg_kernel<256, true, __half, true><<<warpBlk, 256>>>(p_xwh, b1, p_hh, n);

    gemm_mma_kernel<<<g2, 256, SMEM_DYN>>>(p_hh, 256, p_bth2, p_btl2, p_xwh, a2s, a2d, n, 128);
    stats_kernel<<<warpBlk, 256>>>(n);
    agg_kernel<128, false, float, false><<<warpBlk, 256>>>(p_xwh, b2, out, n);
}